// round 14
// baseline (speedup 1.0000x reference)
#include <cuda_runtime.h>
#include <cuda_fp16.h>
#include <math.h>

#define BB 4
#define CC 256
#define NHEAD 8
#define DHEAD 32
#define MF 128
#define NN 9216
#define TT (BB*NN)   /* 36864 */

#define NRM       0.4204482076268573f     /* 32^-0.25 */
#define HALF_NRM2 0.08838834764831845f    /* 0.5 * 32^-0.5 */
#define RATIO     0.08838834764831845f    /* 128^-0.5 */
#define EPSF      1e-4f
#define KP_SCALE  64.0f
#define QP_SCALE  64.0f
#define KP_RATIO  (RATIO*KP_SCALE)
#define QP_RATIO  (RATIO*QP_SCALE)

typedef unsigned long long u64;
typedef unsigned int u32;

/* ---------------- mma.sync helpers ---------------- */
__device__ __forceinline__ u32 smem_u32(const void* p){
    u32 a; asm("{ .reg .u64 t; cvta.to.shared.u64 t, %1; cvt.u32.u64 %0, t; }"
               : "=r"(a) : "l"(p)); return a;
}
#define LDM4(r, a) \
    asm volatile("ldmatrix.sync.aligned.m8n8.x4.shared.b16 {%0,%1,%2,%3}, [%4];" \
        : "=r"((r)[0]),"=r"((r)[1]),"=r"((r)[2]),"=r"((r)[3]) : "r"(a))
#define LDM4T(r, a) \
    asm volatile("ldmatrix.sync.aligned.m8n8.x4.trans.shared.b16 {%0,%1,%2,%3}, [%4];" \
        : "=r"((r)[0]),"=r"((r)[1]),"=r"((r)[2]),"=r"((r)[3]) : "r"(a))
#define MMA16816(c, a, b0, b1) \
    asm volatile("mma.sync.aligned.m16n8k16.row.col.f32.f16.f16.f32 " \
        "{%0,%1,%2,%3}, {%4,%5,%6,%7}, {%8,%9}, {%0,%1,%2,%3};" \
        : "+f"((c)[0]),"+f"((c)[1]),"+f"((c)[2]),"+f"((c)[3]) \
        : "r"((a)[0]),"r"((a)[1]),"r"((a)[2]),"r"((a)[3]), "r"(b0),"r"(b1))
#define CPA16(dst, src) \
    asm volatile("cp.async.cg.shared.global [%0], [%1], 16;" :: "r"(dst), "l"(src))
#define CP_COMMIT() asm volatile("cp.async.commit_group;")
#define CP_WAIT0()  asm volatile("cp.async.wait_group 0;")
#define CP_WAIT1()  asm volatile("cp.async.wait_group 1;")

__device__ __forceinline__ void f16split2(float a, float b, u32 &h, u32 &l){
    __half2 hh = __floats2half2_rn(a, b);
    float2 bk = __half22float2(hh);
    __half2 ll = __floats2half2_rn(a - bk.x, b - bk.y);
    h = *(u32*)&hh; l = *(u32*)&ll;
}
__device__ __forceinline__ float2 h2f(u32 h, u32 l){
    float2 a = __half22float2(*(__half2*)&h);
    float2 b = __half22float2(*(__half2*)&l);
    return make_float2(a.x + b.x, a.y + b.y);
}

/* big-tile GEMM smem: per buffer A 256x32h x2 + B 128x32h x2, pitch 144 */
#define PITCHB 144
#define S2A_H 0
#define S2A_L 36864
#define S2B_H 73728
#define S2B_L 92160
#define BUF2  110592
#define G4_SMEM 221184

/* ---------------- scratch ---------------- */
__device__ u32 g_xh[(size_t)TT*128];
__device__ u32 g_xl[(size_t)TT*128];
__device__ u32 g_qh[(size_t)TT*128];
__device__ u32 g_ql[(size_t)TT*128];
__device__ u32 g_kh[(size_t)TT*128];
__device__ u32 g_kl[(size_t)TT*128];
__device__ u32 g_vh[(size_t)TT*128];
__device__ u32 g_vl[(size_t)TT*128];
__device__ u32 g_ah[(size_t)TT*128];
__device__ u32 g_al[(size_t)TT*128];
__device__ u32 g_wh[3*256*128];
__device__ u32 g_wl[3*256*128];
__device__ u32 g_wch[256*128];
__device__ u32 g_wcl[256*128];
__device__ float g_kmax[32];
__device__ float g_ctx[32*MF*33];
__device__ u32 g_ctxh2[32*64*64];
__device__ u32 g_ctxl2[32*64*64];
__device__ float g_bc[CC];
__device__ u32 g_projh[2048];
__device__ u32 g_projl[2048];

__device__ __forceinline__ void atomicMaxF(float* a, float v){
    int old = __float_as_int(*a);
    while (__int_as_float(old) < v){
        int cur = atomicCAS((int*)a, old, __float_as_int(v));
        if (cur == old) break;
        old = cur;
    }
}

/* ------------------------------------------------------------------ */
__global__ void k_prep(const float* __restrict__ wo, const float* __restrict__ bo,
                       const float* __restrict__ wp, const float* __restrict__ bp){
    __shared__ float row[256];
    int o2 = blockIdx.x;
    int c  = threadIdx.x;
    float s = 0.f;
    for (int o = 0; o < 256; o++) s += wp[o2*256 + o] * wo[o*256 + c];
    row[c] = s;
    if (c == 0){
        float sb = 0.f;
        for (int o = 0; o < 256; o++) sb += wp[o2*256 + o] * bo[o];
        g_bc[o2] = sb + bp[o2];
    }
    __syncthreads();
    if (c < 128){
        u32 h, l;
        f16split2(row[2*c], row[2*c + 1], h, l);
        g_wch[o2*128 + c] = h;
        g_wcl[o2*128 + c] = l;
    }
}

__global__ void k_misc(const float* __restrict__ wq, const float* __restrict__ wk,
                       const float* __restrict__ wv, const float* __restrict__ proj){
    int bid = blockIdx.x, t = threadIdx.x;
    if (bid < 384){
        int i = bid*256 + t;
        int oc = i >> 15, rem = i & 32767;
        int row = rem >> 7, p = rem & 127;
        const float* W = (oc == 0) ? wq : (oc == 1 ? wk : wv);
        u32 h, l;
        f16split2(W[row*256 + p*2], W[row*256 + p*2 + 1], h, l);
        g_wh[i] = h; g_wl[i] = l;
    } else if (bid < 392){
        int i = (bid - 384)*256 + t;
        int m = i >> 4, p = i & 15;
        u32 h, l;
        f16split2(proj[m*32 + p*2]*NRM, proj[m*32 + p*2 + 1]*NRM, h, l);
        g_projh[i] = h; g_projl[i] = l;
        if (bid == 384 && t < 32) g_kmax[t] = -1e30f;
    } else {
        int i = (bid - 392)*256 + t;
        if (i < 32*MF*33) g_ctx[i] = 0.f;
    }
}

__global__ void k_ctx_cvt(){
    int bh = blockIdx.x, t = threadIdx.x;
    for (int i = t; i < 4096; i += 256){
        int j = i >> 6, mp = i & 63;
        float a = 0.f, b = 0.f;
        if (j < 33){
            a = g_ctx[((size_t)bh*MF + mp*2)*33 + j];
            b = g_ctx[((size_t)bh*MF + mp*2 + 1)*33 + j];
        }
        u32 h, l;
        f16split2(a, b, h, l);
        g_ctxh2[bh*4096 + i] = h;
        g_ctxl2[bh*4096 + i] = l;
    }
}

/* ------------------------------------------------------------------ */
/* K_xcvt: transpose+split x -> g_xh/g_xl [token][128 pairs]           */
/* ------------------------------------------------------------------ */
__global__ void __launch_bounds__(256) k_xcvt(const float* __restrict__ x){
    __shared__ u32 sh[128*33];
    __shared__ u32 sl[128*33];
    int tid = threadIdx.x, wid = tid >> 5, lane = tid & 31;
    int t0 = blockIdx.x * 128;
    int b = t0 / NN, tl0 = t0 % NN;
    int tq = lane * 4, cg2 = wid * 2;

    for (int ch = 0; ch < 4; ch++){
        int c0 = ch * 64;
#pragma unroll
        for (int u = 0; u < 4; u++){
            int cl = u*16 + cg2;
            const float* p = &x[((size_t)(b*256 + c0 + cl))*NN + tl0 + tq];
            float4 f0 = *(const float4*)p;
            float4 f1 = *(const float4*)(p + NN);
            const float* e0 = (const float*)&f0;
            const float* e1 = (const float*)&f1;
#pragma unroll
            for (int j = 0; j < 4; j++){
                u32 h, l;
                f16split2(e0[j], e1[j], h, l);
                sh[(tq + j)*33 + (cl >> 1)] = h;
                sl[(tq + j)*33 + (cl >> 1)] = l;
            }
        }
        __syncthreads();
#pragma unroll
        for (int r = 0; r < 16; r++){
            int i = r*256 + tid;
            int row = i >> 5, p = i & 31;
            size_t g = (size_t)(t0 + row)*128 + ch*32 + p;
            g_xh[g] = sh[row*33 + p];
            g_xl[g] = sl[row*33 + p];
        }
        __syncthreads();
    }
}

/* ------------------------------------------------------------------ */
/* big-tile mma body: one K=64 chunk, A 256 rows, B 128 rows, hoisted  */
/* ------------------------------------------------------------------ */
__device__ __forceinline__ void mma_chunk2(u32 base, int wm, int wn, int lane,
                                           float c[4][4][4]){
    u32 a_off = (u32)((wm + (lane & 15))*PITCHB + (lane >> 4)*16);
    u32 b_off = (u32)((wn + (lane & 7) + ((lane >> 4) & 1)*8)*PITCHB
                      + ((lane >> 3) & 1)*16);
#pragma unroll
    for (int ks = 0; ks < 4; ks++){
        u32 ah[4][4], al[4][4], bh[2][4];
#pragma unroll
        for (int mt = 0; mt < 4; mt++)
            LDM4(ah[mt], base + S2A_H + a_off + mt*(16*PITCHB) + ks*32);
#pragma unroll
        for (int np = 0; np < 2; np++)
            LDM4(bh[np], base + S2B_H + b_off + np*(16*PITCHB) + ks*32);
#pragma unroll
        for (int mt = 0; mt < 4; mt++)
            LDM4(al[mt], base + S2A_L + a_off + mt*(16*PITCHB) + ks*32);
#pragma unroll
        for (int mt = 0; mt < 4; mt++)
#pragma unroll
            for (int nt = 0; nt < 4; nt++)
                MMA16816(c[mt][nt], ah[mt], bh[nt>>1][(nt&1)*2], bh[nt>>1][(nt&1)*2+1]);
#pragma unroll
        for (int mt = 0; mt < 4; mt++)
#pragma unroll
            for (int nt = 0; nt < 4; nt++)
                MMA16816(c[mt][nt], al[mt], bh[nt>>1][(nt&1)*2], bh[nt>>1][(nt&1)*2+1]);
        {
            u32 bl[2][4];
#pragma unroll
            for (int np = 0; np < 2; np++)
                LDM4(bl[np], base + S2B_L + b_off + np*(16*PITCHB) + ks*32);
#pragma unroll
            for (int mt = 0; mt < 4; mt++)
#pragma unroll
                for (int nt = 0; nt < 4; nt++)
                    MMA16816(c[mt][nt], ah[mt], bl[nt>>1][(nt&1)*2], bl[nt>>1][(nt&1)*2+1]);
        }
    }
}

__device__ __forceinline__ void copy_chunk2(u32 base, int tid, int ch,
        const u32* pah, const u32* pal, const u32* pbh, const u32* pbl){
#pragma unroll
    for (int it = 0; it < 4; it++){
        int i = it*512 + tid;
        int row = i >> 3, pg = (i & 7)*4;
        size_t ga = (size_t)row*128 + ch*32 + pg;
        u32 off = base + (u32)(row*PITCHB + pg*4);
        CPA16(off + S2A_H, pah + ga);
        CPA16(off + S2A_L, pal + ga);
    }
#pragma unroll
    for (int it = 0; it < 2; it++){
        int i = it*512 + tid;
        int row = i >> 3, pg = (i & 7)*4;
        size_t gb = (size_t)row*128 + ch*32 + pg;
        u32 off = base + (u32)(row*PITCHB + pg*4);
        CPA16(off + S2B_H, pbh + gb);
        CPA16(off + S2B_L, pbl + gb);
    }
}

__device__ __forceinline__ void gemm_pipe2(u32 smb, int tid, int wm, int wn, int lane,
        const u32* pah, const u32* pal, const u32* pbh, const u32* pbl,
        float c[4][4][4]){
    copy_chunk2(smb,        tid, 0, pah, pal, pbh, pbl);
    CP_COMMIT();
    copy_chunk2(smb + BUF2, tid, 1, pah, pal, pbh, pbl);
    CP_COMMIT();
#pragma unroll
    for (int ch = 0; ch < 4; ch++){
        if (ch < 3) CP_WAIT1(); else CP_WAIT0();
        __syncthreads();
        mma_chunk2(smb + (ch & 1)*BUF2, wm, wn, lane, c);
        __syncthreads();
        if (ch < 2){
            copy_chunk2(smb + (ch & 1)*BUF2, tid, ch + 2, pah, pal, pbh, pbl);
            CP_COMMIT();
        }
    }
}

/* ------------------------------------------------------------------ */
/* K1: QKV GEMM — 256x128 tile, 512 thr, double-buffered.              */
/* ------------------------------------------------------------------ */
__global__ void __launch_bounds__(512, 1) k_qkv_t(){
    extern __shared__ char sm[];
    u32 smb = smem_u32(sm);
    int tid = threadIdx.x, wid = tid >> 5, lane = tid & 31;
    int oc = blockIdx.x;
    int t0 = blockIdx.y * 256;
    int wsel = oc >> 1;
    u32* dsth = (oc < 2) ? g_qh : (oc < 4 ? g_kh : g_vh);
    u32* dstl = (oc < 2) ? g_ql : (oc < 4 ? g_kl : g_vl);
    int or0 = (oc & 1) * 128;

    const u32* pah = g_xh + (size_t)t0*128;
    const u32* pal = g_xl + (size_t)t0*128;
    const u32* pbh = g_wh + (size_t)wsel*32768 + (size_t)or0*128;
    const u32* pbl = g_wl + (size_t)wsel*32768 + (size_t)or0*128;

    int wm = (wid >> 2) * 64, wn = (wid & 3) * 32;

    float c[4][4][4];
#pragma unroll
    for (int mt = 0; mt < 4; mt++)
#pragma unroll
        for (int nt = 0; nt < 4; nt++)
#pragma unroll
            for (int r = 0; r < 4; r++) c[mt][nt][r] = 0.f;

    gemm_pipe2(smb, tid, wm, wn, lane, pah, pal, pbh, pbl, c);

    u32* SH = (u32*)sm;
    u32* SL = (u32*)(sm + 69632);
#pragma unroll
    for (int mt = 0; mt < 4; mt++){
#pragma unroll
        for (int nt = 0; nt < 4; nt++){
            int r = wm + mt*16 + (lane >> 2);
            int cp = (wn + nt*8 + (lane & 3)*2) >> 1;
            u32 h, l;
            f16split2(c[mt][nt][0], c[mt][nt][1], h, l);
            SH[r*68 + cp] = h; SL[r*68 + cp] = l;
            f16split2(c[mt][nt][2], c[mt][nt][3], h, l);
            SH[(r+8)*68 + cp] = h; SL[(r+8)*68 + cp] = l;
        }
    }
    __syncthreads();
#pragma unroll
    for (int it = 0; it < 8; it++){
        int i = it*512 + tid;
        int row = i >> 4, c4 = (i & 15)*4;
        size_t g = (size_t)(t0 + row)*128 + (or0 >> 1) + c4;
        *(uint4*)&dsth[g] = *(uint4*)&SH[row*68 + c4];
        *(uint4*)&dstl[g] = *(uint4*)&SL[row*68 + c4];
    }
}

/* ------------------------------------------------------------------ */
/* K5: final GEMM — 256x128 tile, 512 thr, double-buffered.            */
/* ------------------------------------------------------------------ */
__global__ void __launch_bounds__(512, 1) k_final_t(float* __restrict__ out){
    extern __shared__ char sm[];
    u32 smb = smem_u32(sm);
    int tid = threadIdx.x, wid = tid >> 5, lane = tid & 31;
    int o0 = blockIdx.x * 128;
    int t0 = blockIdx.y * 256;
    int b = t0 / NN, tl0 = t0 % NN;

    const u32* pah = g_ah + (size_t)t0*128;
    const u32* pal = g_al + (size_t)t0*128;
    const u32* pbh = g_wch + (size_t)o0*128;
    const u32* pbl = g_wcl + (size_t)o0*128;

    int wm = (wid >> 2) * 64, wn = (wid & 3) * 32;

    float c[4][4][4];
#pragma unroll
    for (int mt = 0; mt < 4; mt++)
#pragma unroll
        for (int nt = 0; nt < 4; nt++)
#pragma unroll
            for (int r = 0; r < 4; r++) c[mt][nt][r] = 0.f;

    gemm_pipe2(smb, tid, wm, wn, lane, pah, pal, pbh, pbl, c);

    float* stage = (float*)sm;
#pragma unroll
    for (int mt = 0; mt < 4; mt++){
#pragma unroll
        for (int nt = 0; nt < 4; nt++){
            int r = wm + mt*16 + (lane >> 2);
            int cc = wn + nt*8 + (lane & 3)*2;
            stage[cc*260 + r]         = c[mt][nt][0];
            stage[(cc+1)*260 + r]     = c[mt][nt][1];
            stage[cc*260 + r + 8]     = c[mt][nt][2];
            stage[(cc+1)*260 + r + 8] = c[mt][nt][3];
        }
    }
    __syncthreads();
#pragma unroll
    for (int i2 = 0; i2 < 16; i2++){
        int idx = i2*512 + tid;
        int cc = idx >> 6, t4 = (idx & 63) * 4;
        int o = o0 + cc;
        float bias = g_bc[o];
        float4 v = *(float4*)&stage[cc*260 + t4];
        v.x += bias; v.y += bias; v.z += bias; v.w += bias;
        *(float4*)&out[((size_t)b*256 + o)*NN + tl0 + t4] = v;
    }
}

/* ------------------------------------------------------------------ */
/* K2: key-dash max — 2 tiles of 128 tokens per block. grid (36, 32).  */
/* ------------------------------------------------------------------ */
__global__ void __launch_bounds__(256) k_kmax(){
    __shared__ u32 projh[128*20];
    __shared__ u32 projl[128*20];
    __shared__ u32 kth[128*20];
    __shared__ u32 ktl[128*20];
    __shared__ float red[256];
    int bh = blockIdx.y, b = bh >> 3, h = bh & 7;
    int t = threadIdx.x, wid = t >> 5, lane = t & 31;

#pragma unroll
    for (int r = 0; r < 2; r++){
        int i = r*256 + t;
        int m = i >> 2, q4 = (i & 3)*4;
        *(uint4*)&projh[m*20 + q4] = *(const uint4*)&g_projh[m*16 + q4];
        *(uint4*)&projl[m*20 + q4] = *(const uint4*)&g_projl[m*16 + q4];
    }

    int wm = (wid >> 1)*32, wn = (wid & 1)*64;
    u32 smPH = smem_u32(projh), smPL = smem_u32(projl);
    u32 smKH = smem_u32(kth),   smKL = smem_u32(ktl);
    u32 a_off = (u32)((wm + (lane & 15))*80 + (lane >> 4)*16);
    u32 b_off = (u32)((wn + (lane & 7) + ((lane >> 4) & 1)*8)*80 + ((lane >> 3) & 1)*16);

    float mx = -1e30f;
    for (int tile = 0; tile < 2; tile++){
        int n0 = blockIdx.x * 256 + tile * 128;
#pragma unroll
        for (int r = 0; r < 2; r++){
            int i = r*256 + t;
            int m = i >> 2, q4 = (i & 3)*4;
            size_t g = (size_t)(b*NN + n0 + m)*128 + h*16 + q4;
            *(uint4*)&kth[m*20 + q4] = *(const uint4*)&g_kh[g];
            *(uint4*)&ktl[m*20 + q4] = *(const uint4*)&g_kl[g];
        }
        __syncthreads();

        float c[2][8][4];
#pragma unroll
        for (int mt = 0; mt < 2; mt++)
#pragma unroll
            for (int nt = 0; nt < 8; nt++)
#pragma unroll
                for (int r = 0; r < 4; r++) c[mt][nt][r] = 0.f;
#pragma unroll
        for (int ks = 0; ks < 2; ks++){
            u32 ah[2][4], al[2][4], bh2[4][4];
#pragma unroll
            for (int mt = 0; mt < 2; mt++)
                LDM4(ah[mt], smPH + a_off + mt*(16*80) + ks*32);
#pragma unroll
            for (int np = 0; np < 4; np++)
                LDM4(bh2[np], smKH + b_off + np*(16*80) + ks*32);
#pragma unroll
            for (int mt = 0; mt < 2; mt++)
                LDM4(al[mt], smPL + a_off + mt*(16*80) + ks*32);
#pragma unroll
            for (int mt = 0; mt < 2; mt++)
#pragma unroll
                for (int nt = 0; nt < 8; nt++)
                    MMA16816(c[mt][nt], ah[mt], bh2[nt>>1][(nt&1)*2], bh2[nt>>1][(nt&1)*2+1]);
#pragma unroll
            for (int mt = 0; mt < 2; mt++)
#pragma unroll
                for (int nt = 0; nt < 8; nt++)
                    MMA16816(c[mt][nt], al[mt], bh2[nt>>1][(nt&1)*2], bh2[nt>>1][(nt&1)*2+1]);
            {
                u32 bl[4][4];
#pragma unroll
                for (int np = 0; np < 4; np++)
                    LDM4(bl[np], smKL + b_off + np*(16*80) + ks*32);
#pragma unroll
                for (int mt = 0; mt < 2; mt++)
#pragma unroll
                    for (int nt = 0; nt < 8; nt++)
                        MMA16816(c[mt][nt], ah[mt], bl[nt>>1][(nt&1)*2], bl[nt>>1][(nt&1)*2+1]);
            }
        }
#pragma unroll
        for (int mt = 0; mt < 2; mt++)
#pragma unroll
            for (int nt = 0; nt < 8; nt++)
#pragma unroll
                for (int r = 0; r < 4; r++) mx = fmaxf(mx, c[mt][nt][r]);
        __syncthreads();
    }
    red[t] = mx;
    __syncthreads();
    for (int s = 128; s > 0; s >>= 1){
        if (t < (unsigned)s) red[t] = fmaxf(red[t], red[t + s]);
        __syncthreads();
    }
    if (t == 0) atomicMaxF(&g_kmax[bh], red[0]);
}

/* ------------------------------------------------------------------ */
/* K3: fused key features + ctx. grid (9, 32) — one full wave.         */
/* ------------------------------------------------------------------ */
#define CP_PROJH 0
#define CP_PROJL 10240
#define CP_KTH   20480
#define CP_KTL   25600
#define CP_KPSH  30720
#define CP_KPSL  49152
#define CP_VTH   67584
#define CP_VTL   74752
#define CP_DIAG  81920
#define CTX_SMEM 82176
#define CTX_SPLITS 9
#define CTX_TILES  16

__global__ void __launch_bounds__(256) k_ctx2(){
    extern __shared__ char sm[];
    u32 smb = smem_u32(sm);
    int bh = blockIdx.y, b = bh >> 3, h = bh & 7;
    int sp = blockIdx.x;
    int t = threadIdx.x, wid = t >> 5, lane = t & 31;
    float gmax = g_kmax[bh];

    u32* PJH = (u32*)(sm + CP_PROJH); u32* PJL = (u32*)(sm + CP_PROJL);
    u32* KTH = (u32*)(sm + CP_KTH);   u32* KTL = (u32*)(sm + CP_KTL);
    u32* VTH = (u32*)(sm + CP_VTH);   u32* VTL = (u32*)(sm + CP_VTL);
    float* DIAG = (float*)(sm + CP_DIAG);

#pragma unroll
    for (int r = 0; r < 2; r++){
        int i = r*256 + t;
        int m = i >> 2, q4 = (i & 3)*4;
        *(uint4*)&PJH[m*20 + q4] = *(const uint4*)&g_projh[m*16 + q4];
        *(uint4*)&PJL[m*20 + q4] = *(const uint4*)&g_projl[m*16 + q4];
    }
    for (int i = t; i < 1536; i += 256){
        int mat = (i >= 768), rem = (i >= 768) ? i - 768 : i;
        int tok = rem / 12, cc = 16 + rem % 12;
        u32 v = (mat == 0 && cc == 16) ? 0x00003C00u : 0u;
        ((mat == 0) ? VTH : VTL)[tok*28 + cc] = v;
    }

    int wm1 = (wid >> 1)*32, wn1 = (wid & 1)*32;
    u32 a1_off = (u32)((wm1 + (lane & 15))*80 + (lane >> 4)*16);
    u32 b1_off = (u32)((wn1 + (lane & 7) + ((lane >> 4) & 1)*8)*80 + ((lane >> 3) & 1)*16);
    int wm2 = (wid >> 1)*32, wn2 = (wid & 1)*24;
    u32 a2_off = (u32)((wm2 + (lane & 15))*144 + (lane >> 4)*16);
    u32 b2row = (u32)(((lane & 7) + ((lane >> 3) & 1)*8)*112);
    u32 b2col0 = (u32)((wn2 + ((lane >> 4) & 1)*8)*2);

    float c2[2][3][4];
#pragma unroll
    for (int mt = 0; mt < 2; mt++)
#pragma unroll
        for (int nt = 0; nt < 3; nt++)
#pragma unroll
            for (int r = 0; r < 4; r++) c2[mt][nt][r] = 0.f;

    for (int it = 0; it < CTX_TILES; it++){
        int n0 = sp*(CTX_TILES*64) + it*64;
        {
            int tok = t >> 2, q4 = (t & 3)*4;
            size_t g = (size_t)(b*NN + n0 + tok)*128 + h*16 + q4;
            *(uint4*)&KTH[tok*20 + q4] = *(const uint4*)&g_kh[g];
            *(uint4*)&KTL[tok*20 + q4] = *(const uint4*)&g_kl[g];
            *(uint4*)&VTH[tok*28 + q4] = *(const uint4*)&g_vh[g];
            *(uint4*)&VTL[tok*28 + q4] = *(const uint4*)&g_vl[g];
        }
        __syncthreads();
        if (t < 64){
            float sq = 0.f;
#pragma unroll
            for (int i = 0; i < 16; i++){
                float2 v = h2f(KTH[t*20 + i], KTL[t*20 + i]);
                sq += v.x*v.x + v.y*v.y;
            }
            DIAG[t] = HALF_NRM2 * sq;
        }
        __syncthreads();

        float c1[2][4][4];
#pragma unroll
        for (int mt = 0; mt < 2; mt++)
#pragma unroll
            for (int nt = 0; nt < 4; nt++)
#pragma unroll
                for (int r = 0; r < 4; r++) c1[mt][nt][r] = 0.f;
#pragma unroll
        for (int ks = 0; ks < 2; ks++){
            u32 ah[2][4], al[2][4], bhh[2][4];
#pragma unroll
            for (int mt = 0; mt < 2; mt++)
                LDM4(ah[mt], smb + CP_PROJH + a1_off + mt*(16*80) + ks*32);
#pragma unroll
            for (int np = 0; np < 2; np++)
                LDM4(bhh[np], smb + CP_KTH + b1_off + np*(16*80) + ks*32);
#pragma unroll
            for (int mt = 0; mt < 2; mt++)
                LDM4(al[mt], smb + CP_PROJL + a1_off + mt*(16*80) + ks*32);
#pragma unroll
            for (int mt = 0; mt < 2; mt++)
#pragma unroll
                for (int nt = 0; nt < 4; nt++)
                    MMA16816(c1[mt][nt], ah[mt], bhh[nt>>1][(nt&1)*2], bhh[nt>>1][(nt&1)*2+1]);
#pragma unroll
            for (int mt = 0; mt < 2; mt++)
#pragma unroll
                for (int nt = 0; nt < 4; nt++)
                    MMA16816(c1[mt][nt], al[mt], bhh[nt>>1][(nt&1)*2], bhh[nt>>1][(nt&1)*2+1]);
            {
                u32 bl[2][4];
#pragma unroll
                for (int np = 0; np < 2; np++)
                    LDM4(bl[np], smb + CP_KTL + b1_off + np*(16*80) + ks*32);
#pragma unroll
                for (int mt = 0; mt < 2; mt++)
#pragma unroll
                    for (int nt = 0; nt < 4; nt++)
                        MMA16816(c1[mt][nt], ah[mt], bl[nt>>1][(nt&1)*2], bl[nt>>1][(nt&1)*2+1]);
            }
        }
        u32* KPH = (u32*)(sm + CP_KPSH);
        u32* KPL = (u32*)(sm + CP_KPSL);
#pragma unroll
        for (int mt = 0; mt < 2; mt++){
#pragma unroll
            for (int nt = 0; nt < 4; nt++){
                int col = wn1 + nt*8 + (lane & 3)*2;
                float d0 = DIAG[col] + gmax, d1 = DIAG[col+1] + gmax;
                int r0 = wm1 + mt*16 + (lane >> 2);
                float v0 = KP_RATIO*(__expf(c1[mt][nt][0] - d0) + EPSF);
                float v1 = KP_RATIO*(__expf(c1[mt][nt][1] - d1) + EPSF);
                float v2 = KP_RATIO*(__expf(c1[mt][nt][2] - d0) + EPSF);
                float v3 = KP_RATIO*(__expf(c1[mt][nt][3] - d1) + EPSF);
                u32 hh, ll;
                f16split2(v0, v1, hh, ll);
                KPH[r0*36 + (col>>1)] = hh; KPL[r0*36 + (col>>1)] = ll;
                f16split2(v2, v3, hh, ll);
                KPH[(r0+8)*36 + (col>>1)] = hh; KPL[(r0+8)*36 + (col>>1)] = ll;
            }
        }
        __syncthreads();

#pragma unroll
        for (int ks = 0; ks < 4; ks++){
            u32 ah[2][4], al[2][4], bhh[2][4];
            u32 rb = (u32)(ks*16*112) + b2row;
#pragma unroll
            for (int mt = 0; mt < 2; mt++)
                LDM4(ah[mt], smb + CP_KPSH + a2_off + mt*(16*144) + ks*32);
#pragma unroll
            for (int np = 0; np < 2; np++)
                LDM4T(bhh[np], smb + CP_VTH + rb + b2col0 + np*32);
#pragma unroll
            for (int mt = 0; mt < 2; mt++)
                LDM4(al[mt], smb + CP_KPSL + a2_off + mt*(16*144) + ks*32);
#pragma unroll
            for (int mt = 0; mt < 2; mt++)
#pragma unroll
                for (int nt = 0; nt < 3; nt++)
                    MMA16816(c2[mt][nt], ah[mt], bhh[nt>>1][(nt&1)*2], bhh[nt>>1][(nt&1)*2+1]);
#pragma unroll
            for (int mt = 0; mt < 2; mt++)
#pragma unroll
                for (int nt = 0; nt < 3; nt++)
                    MMA16816(c2[mt][nt], al[mt], bhh[nt>>1][(nt&1)*2], bhh[nt>>1][(nt&1)*2+1]);
            {
                u32 bl[2][4];
#pragma unroll
                for (int np = 0; np < 2; np++)
                    LDM4T(bl[np], smb + CP_VTL + rb + b2col0 + np*32);
#pragma unroll
                for (int mt = 0; mt < 2; mt++)
#pragma unroll
                    for (int nt = 0; nt < 3; nt++)
                        MMA16816(c2[mt][nt], ah[mt], bl[nt>>1][(nt&1)*2], bl[nt>>1][(nt&1)*2+1]);
            }
        }
        __syncthreads();
    }

#pragma unroll
    for (int mt = 0; mt < 2; mt++){
#pragma unroll
        for (int nt = 0; nt < 3; nt++){
            int m = wm2 + mt*16 + (lane >> 2);
            int n = wn2 + nt*8 + (lane & 3)*2;
            size_t base = ((size_t)bh*MF + m)*33;
            if (n < 33)   atomicAdd(&g_ctx[base + n],     c2[mt][nt][0]);
            if (n+1 < 33) atomicAdd(&g_ctx[base + n + 1], c2[mt][nt][1]);
            if (n < 33)   atomicAdd(&g_ctx[base + 264 + n],     c2[mt][nt][2]);
            if (n+1 < 33) atomicAdd(&g_ctx[base + 264 + n + 1], c2[mt][nt][3]);
        }
    }
}

/* ------------------------------------------------------------------ */
/* K4: fused query features + qp@ctx + d_inv.                          */
/* 2 tiles/block; mma2 halved to j<32; warps 4-7 compute denominator   */
/* in fp32. grid (72, 32), 256 thr.                                    */
/* ------------------------------------------------------------------ */
#define QP_PROJH 0
#define QP_PROJL 10240
#define QP_QTH   20480
#define QP_QTL   25600
#define QP_QPSH  30720
#define QP_QPSL  49152
#define QP_CTH   67584
#define QP_CTL   84992
#define QP_PM    102400
#define QP_RMAX  103424      /* reused as DEN after qps written */
#define QP_DIAG  103680
#define QP_C32F  103936      /* ctx32f[128] floats */
#define QP_STG   QP_QPSH
#define QA_SMEM  104448

__global__ void __launch_bounds__(256) k_qattn2(){
    extern __shared__ char sm[];
    u32 smb = smem_u32(sm);
    int bh = blockIdx.y, b = bh >> 3, h = bh & 7;
    int t = threadIdx.x, wid = t >> 5, lane = t & 31;

    u32* PJH = (u32*)(sm + QP_PROJH); u32* PJL = (u32*)(sm + QP_PROJL);
    u32* QTH = (u32*)(sm + QP_QTH);   u32* QTL = (u32*)(sm + QP_QTL);
    u32* CTH = (u32*)(sm + QP_CTH);   u32* CTL = (u32*)(sm + QP_CTL);
    float* PM = (float*)(sm + QP_PM);
    float* RMAX = (float*)(sm + QP_RMAX);
    float* DEN  = (float*)(sm + QP_RMAX);   /* alias: RMAX dead after qps */
    float* DIAG = (float*)(sm + QP_DIAG);
    float* C32F = (float*)(sm + QP_C32F);

#pragma unroll
    for (int r = 0; r < 2; r++){
        int i = r*256 + t;
        int m = i >> 2, q4 = (i & 3)*4;
        *(uint4*)&PJH[m*20 + q4] = *(const uint4*)&g_projh[m*16 + q4];
        *(uint4*)&PJL[m*20 + q4] = *(const uint4*)&g_projl[m*16 + q4];
    }
#pragma unroll
    for (int r = 0; r < 4; r++){
        int i = r*256 + t;
        int j = i >> 4, q4 = (i & 15)*4;
        *(uint4*)&CTH[j*68 + q4] = *(const uint4*)&g_ctxh2[bh*4096 + j*64 + q4];
        *(uint4*)&CTL[j*68 + q4] = *(const uint4*)&g_ctxl2[bh*4096 + j*64 + q4];
    }
    __syncthreads();
    /* ctx32f = fp32 reconstruction of ctx column j=32 (ksum) */
    if (t < 64){
        float2 v = h2f(CTH[32*68 + t], CTL[32*68 + t]);
        C32F[2*t]     = v.x;
        C32F[2*t + 1] = v.y;
    }

    int wm1 = (wid >> 1)*32, wn1 = (wid & 1)*32;
    u32 a1_off = (u32)((wm1 + (lane & 15))*80 + (lane >> 4)*16);
    u32 b1_off = (u32)((wn1 + (lane & 7) + ((lane >> 4) & 1)*8)*80 + ((lane >> 3) & 1)*16);
    /* mma2 (warps 0-3): j 0..31 */
    int wm2 = (wid >> 1)*16, wn2 = (wid & 1)*32;
    u32 a2_off = (u32)((wm2 + (lane & 15))*272 + (lane >> 4)*16);
    u32* QPH = (u32*)(sm + QP_QPSH);
    u32* QPL = (u32*)(sm + QP_QPSL);

    for (int tile = 0; tile < 2; tile++){
        int n0 = blockIdx.x * 128 + tile * 64;
        {
            int tok = t >> 2, q4 = (t & 3)*4;
            size_t g = (size_t)(b*NN + n0 + tok)*128 + h*16 + q4;
            *(uint4*)&QTH[tok*20 + q4] = *(const uint4*)&g_qh[g];
            *(uint4*)&QTL[tok*20 + q4] = *(const uint4*)&g_ql[g];
        }
        __syncthreads();
        if (t < 64){
            float sq = 0.f;
#pragma unroll
            for (int i = 0; i < 16; i++){
                float2 v = h2f(QTH[t*20 + i], QTL[t*20 + i]);
                sq += v.x*v.x + v.y*v.y;
            }
            DIAG[t] = HALF_NRM2 * sq;
        }
        __syncthreads();

        float c1[2][4][4];
#pragma unroll
        for (int mt = 0; mt < 2; mt++)
#pragma unroll
            for (int nt = 0; nt < 4; nt++)
#pragma unroll
                for (int r = 0; r < 4; r++) c1[mt][nt][r] = 0.f;
#pragma unroll
        for (int ks = 0; ks < 2; ks++){
            u32 ah[2][4], al[2][4], bhh[2][4];
#pragma unroll
            for (int mt = 0; mt < 2; mt++)
                LDM4(ah[mt], smb + QP_PROJH + a1_off + mt*(16*80) + ks*32);
#pragma unroll
            for (int np = 0; np < 2; np++)
                LDM4(bhh[np], smb + QP_QTH + b1_off + np*(16*80) + ks*32);
#pragma unroll
            for (int mt = 0; mt < 2; mt++)
                LDM4(al[mt], smb + QP_PROJL + a1_off + mt*(16*80) + ks*32);
#pragma unroll
            for (int mt = 0; mt < 2; mt++)
#pragma unroll
                for (int nt = 0; nt < 4; nt++)
                    MMA16816(c1[mt][nt], ah[mt], bhh[nt>>1][(nt&1)*2], bhh[nt>>1][(nt&1)*2+1]);
#pragma unroll
            for (int mt = 0; mt < 2; mt++)
#pragma unroll
                for (int nt = 0; nt < 4; nt++)
                    MMA16816(c1[mt][nt], al[mt], bhh[nt>>1][(nt&1)*2], bhh[nt>>1][(nt&1)*2+1]);
            {
                u32 bl[2][4];
#pragma unroll
                for (int np = 0; np < 2; np++)
                    LDM4(bl[np], smb + QP_QTL + b1_off + np*(16*80) + ks*32);
#pragma unroll
                for (int mt = 0; mt < 2; mt++)
#pragma unroll
                    for (int nt = 0; nt < 4; nt++)
                        MMA16816(c1[mt][nt], ah[mt], bl[nt>>1][(nt&1)*2], bl[nt>>1][(nt&1)*2+1]);
            }
        }

#pragma unroll
        for (int nt = 0; nt < 4; nt++){
            float me = fmaxf(fmaxf(c1[0][nt][0], c1[0][nt][2]),
                             fmaxf(c1[1][nt][0], c1[1][nt][2]));
            float mo = fmaxf(fmaxf(c1[0][nt][1], c1[0][nt][3]),
                             fmaxf(c1[1][nt][1], c1[1][nt][3]));
#pragma unroll
            for (int s = 4; s < 32; s <<= 1){
                me = fmaxf(me, __shfl_xor_sync(0xFFFFFFFF, me, s));
                mo = fmaxf(mo, __shfl_xor_sync(0xFFFFFFFF, mo, s));
            }
            if ((lane >> 2) == 0){
                int col = wn1 + nt*8 + (lane & 3)*2;
                PM[(wid >> 1)*64 + col]     = me;
                PM[(wid >> 1)*64 + col + 1] = mo;
            }
        }
        __syncthreads();
        if (t < 64){
            float mx = PM[t];
            mx = fmaxf(mx, PM[64 + t]);
            mx = fmaxf(mx, PM[128 + t]);
            mx = fmaxf(mx, PM[192 + t]);
            RMAX[t] = mx;
        }
        __syncthreads();

        {
#pragma unroll
            for (int mt = 0; mt < 2; mt++){
#pragma unroll
                for (int nt = 0; nt < 4; nt++){
                    int col = wn1 + nt*8 + (lane & 3)*2;
                    float d0 = DIAG[col] + RMAX[col], d1 = DIAG[col+1] + RMAX[col+1];
                    int r0 = wm1 + mt*16 + (lane >> 2);
                    float v0 = QP_RATIO*(__expf(c1[mt][nt][0] - d0) + EPSF);
                    float v1 = QP_RATIO*(__expf(c1[mt][nt][1] - d1) + EPSF);
                    float v2 = QP_RATIO*(__expf(c1[mt][nt][2] - d0) + EPSF);
                    float v3 = QP_RATIO*(__expf(c1[mt][nt][3] - d1) + EPSF);
                    u32 hh, ll;
                    f16split2(v0, v1, hh, ll);
                    QPH[r0*36 + (col>>1)] = hh; QPL[r0*36 + (col>>1)] = ll;
                    f16split2(v2, v3, hh, ll);
                    QPH[(r0+8)*36 + (col>>1)] = hh; QPL[(r0+8)*36 + (col>>1)] = ll;
                }
            }
        }
        __syncthreads();

        float c2[4][4];
        if (wid < 4){
            /* mma2: j 0..31 only */
#pragma unroll
            for (int nt = 0; nt < 4; nt++)
#pragma unroll
                for (int r = 0; r < 4; r++) c2[nt][r] = 0.f;
#pragma unroll
            for (int ks = 0; ks < 8; ks++){
                u32 ah[4], al[4], bt[2][4], btl[2][4];
                LDM4(ah, smb + QP_CTH + a2_off + ks*32);
                LDM4(al, smb + QP_CTL + a2_off + ks*32);
                u32 rowb = (u32)((ks*16 + (lane & 7) + ((lane >> 3) & 1)*8)*144);
#pragma unroll
                for (int np = 0; np < 2; np++){
                    u32 colb = (u32)((wn2 + np*16 + ((lane >> 4) & 1)*8)*2);
                    LDM4T(bt[np],  smb + QP_QPSH + rowb + colb);
                    LDM4T(btl[np], smb + QP_QPSL + rowb + colb);
                }
#pragma unroll
                for (int nt = 0; nt < 4; nt++){
                    MMA16816(c2[nt], ah, bt[nt>>1][(nt&1)*2],  bt[nt>>1][(nt&1)*2+1]);
                    MMA16816(c2[nt], ah, btl[nt>>1][(nt&1)*2], btl[nt>>1][(nt&1)*2+1]);
                    MMA16816(c2[nt], al, bt[nt>>1][(nt&1)*2],  bt[nt>>1][(nt&1)*2+1]);
                }
            }
        } else {
            /* denominator: warp w handles toks (w-4)*16..+15, 2 lanes/tok */
            int tok = (wid - 4)*16 + (lane >> 1);
            int mh  = (lane & 1)*64;
            int tp  = tok >> 1, hi = tok & 1;
            float den = 0.f;
#pragma unroll 8
            for (int m = 0; m < 64; m++){
                float2 qv = h2f(QPH[(mh + m)*36 + tp], QPL[(mh + m)*36 + tp]);
                float q = hi ? qv.y : qv.x;
                den += q * C32F[mh + m];
            }
            den += __shfl_xor_sync(0xFFFFFFFF, den, 1);
            if ((lane & 1) == 0) DEN[tok] = den;
        }
        __syncthreads();

        float* STG = (float*)(sm + QP_STG);
        if (wid < 4){
#pragma unroll
            for (int nt = 0; nt < 4; nt++){
                int j = wm2 + (lane >> 2);
                int tok = wn2 + nt*8 + (lane & 3)*2;
                STG[j*68 + tok]         = c2[nt][0];
                STG[j*68 + tok + 1]     = c2[nt][1];
                STG[(j+8)*68 + tok]     = c2[nt][2];
                STG[(j+8)*68 + tok + 1] = c2[nt][3];
            }
        }
        __syncthreads();

        {
            int tok = t >> 2, jb = (t & 3)*8;
            float inv = 1.0f / DEN[tok];
            u32 hv[4], lv[4];
#pragma unroll
            for (int p = 0; p < 4; p++){
                float v0 = STG[(jb + 2*p)*68 + tok] * inv;
                float v1 = STG[(jb + 2*p + 1)*68 + tok] * inv;
                f16split2(v0, v1, hv[p], lv[p]);
            }
            size_t base = (size_t)(b*NN + n0 + tok)*128 + h*16 + (jb >> 1);
            *(uint4*)&g_ah[base] = make_uint4(hv[0], hv[1], hv[2], hv[3]);
            *(uint4*)&g_al[base] = make_uint4(lv[0], lv[1], lv[2], lv[3]);
        }
        __syncthreads();
    }
}

/* ------------------------------------------------------------------ */
extern "C" void kernel_launch(void* const* d_in, const int* in_sizes, int n_in,
                              void* d_out, int out_size){
    const float* x    = (const float*)d_in[0];
    const float* wq   = (const float*)d_in[1];
    const float* wk   = (const float*)d_in[2];
    const float* wv   = (const float*)d_in[3];
    const float* wo   = (const float*)d_in[4];
    const float* bo   = (const float*)d_in[5];
    const float* proj = (const float*)d_in[6];
    const float* wp   = (const float*)d_in[7];
    const float* bp   = (const float*)d_in[8];
    float* out = (float*)d_out;

    cudaFuncSetAttribute(k_qkv_t,   cudaFuncAttributeMaxDynamicSharedMemorySize, G4_SMEM);
    cudaFuncSetAttribute(k_final_t, cudaFuncAttributeMaxDynamicSharedMemorySize, G4_SMEM);
    cudaFuncSetAttribute(k_ctx2,    cudaFuncAttributeMaxDynamicSharedMemorySize, CTX_SMEM);
    cudaFuncSetAttribute(k_qattn2,  cudaFuncAttributeMaxDynamicSharedMemorySize, QA_SMEM);

    k_prep<<<256, 256>>>(wo, bo, wp, bp);
    k_misc<<<920, 256>>>(wq, wk, wv, proj);
    k_xcvt<<<TT/128, 256>>>(x);
    k_qkv_t<<<dim3(6, TT/256), 512, G4_SMEM>>>();
    k_kmax<<<dim3(NN/256, 32), 256>>>();
    k_ctx2<<<dim3(CTX_SPLITS, 32), 256, CTX_SMEM>>>();
    k_ctx_cvt<<<32, 256>>>();
    k_qattn2<<<dim3(NN/128, 32), 256, QA_SMEM>>>();
    k_final_t<<<dim3(2, TT/256), 512, G4_SMEM>>>(out);
}

// round 15
// speedup vs baseline: 1.0515x; 1.0515x over previous
#include <cuda_runtime.h>
#include <cuda_fp16.h>
#include <math.h>

#define BB 4
#define CC 256
#define NHEAD 8
#define DHEAD 32
#define MF 128
#define NN 9216
#define TT (BB*NN)   /* 36864 */

#define NRM       0.4204482076268573f     /* 32^-0.25 */
#define HALF_NRM2 0.08838834764831845f    /* 0.5 * 32^-0.5 */
#define RATIO     0.08838834764831845f    /* 128^-0.5 */
#define EPSF      1e-4f
#define KP_SCALE  64.0f
#define QP_SCALE  64.0f
#define KP_RATIO  (RATIO*KP_SCALE)
#define QP_RATIO  (RATIO*QP_SCALE)

typedef unsigned long long u64;
typedef unsigned int u32;

/* ---------------- mma.sync helpers ---------------- */
__device__ __forceinline__ u32 smem_u32(const void* p){
    u32 a; asm("{ .reg .u64 t; cvta.to.shared.u64 t, %1; cvt.u32.u64 %0, t; }"
               : "=r"(a) : "l"(p)); return a;
}
#define LDM4(r, a) \
    asm volatile("ldmatrix.sync.aligned.m8n8.x4.shared.b16 {%0,%1,%2,%3}, [%4];" \
        : "=r"((r)[0]),"=r"((r)[1]),"=r"((r)[2]),"=r"((r)[3]) : "r"(a))
#define LDM4T(r, a) \
    asm volatile("ldmatrix.sync.aligned.m8n8.x4.trans.shared.b16 {%0,%1,%2,%3}, [%4];" \
        : "=r"((r)[0]),"=r"((r)[1]),"=r"((r)[2]),"=r"((r)[3]) : "r"(a))
#define MMA16816(c, a, b0, b1) \
    asm volatile("mma.sync.aligned.m16n8k16.row.col.f32.f16.f16.f32 " \
        "{%0,%1,%2,%3}, {%4,%5,%6,%7}, {%8,%9}, {%0,%1,%2,%3};" \
        : "+f"((c)[0]),"+f"((c)[1]),"+f"((c)[2]),"+f"((c)[3]) \
        : "r"((a)[0]),"r"((a)[1]),"r"((a)[2]),"r"((a)[3]), "r"(b0),"r"(b1))
#define CPA16(dst, src) \
    asm volatile("cp.async.cg.shared.global [%0], [%1], 16;" :: "r"(dst), "l"(src))
#define CP_COMMIT() asm volatile("cp.async.commit_group;")
#define CP_WAIT0()  asm volatile("cp.async.wait_group 0;")
#define CP_WAIT1()  asm volatile("cp.async.wait_group 1;")

__device__ __forceinline__ void f16split2(float a, float b, u32 &h, u32 &l){
    __half2 hh = __floats2half2_rn(a, b);
    float2 bk = __half22float2(hh);
    __half2 ll = __floats2half2_rn(a - bk.x, b - bk.y);
    h = *(u32*)&hh; l = *(u32*)&ll;
}
__device__ __forceinline__ float2 h2f(u32 h, u32 l){
    float2 a = __half22float2(*(__half2*)&h);
    float2 b = __half22float2(*(__half2*)&l);
    return make_float2(a.x + b.x, a.y + b.y);
}

/* big-tile GEMM smem: per buffer A 256x32h x2 + B 128x32h x2, pitch 144 */
#define PITCHB 144
#define S2A_H 0
#define S2A_L 36864
#define S2B_H 73728
#define S2B_L 92160
#define BUF2  110592
#define G4_SMEM 221184

/* ---------------- scratch ---------------- */
__device__ u32 g_xh[(size_t)TT*128];
__device__ u32 g_xl[(size_t)TT*128];
__device__ u32 g_qh[(size_t)TT*128];
__device__ u32 g_ql[(size_t)TT*128];
__device__ u32 g_kh[(size_t)TT*128];
__device__ u32 g_kl[(size_t)TT*128];
__device__ u32 g_vh[(size_t)TT*128];
__device__ u32 g_vl[(size_t)TT*128];
__device__ u32 g_ah[(size_t)TT*128];
__device__ u32 g_al[(size_t)TT*128];
__device__ u32 g_wh[3*256*128];
__device__ u32 g_wl[3*256*128];
__device__ u32 g_wch[256*128];
__device__ u32 g_wcl[256*128];
__device__ float g_kmax[32];
__device__ float g_ctx[32*MF*33];
__device__ u32 g_ctxh2[32*64*64];
__device__ u32 g_ctxl2[32*64*64];
__device__ float g_bc[CC];
__device__ u32 g_projh[2048];
__device__ u32 g_projl[2048];

__device__ __forceinline__ void atomicMaxF(float* a, float v){
    int old = __float_as_int(*a);
    while (__int_as_float(old) < v){
        int cur = atomicCAS((int*)a, old, __float_as_int(v));
        if (cur == old) break;
        old = cur;
    }
}

/* ------------------------------------------------------------------ */
/* K_misc: Wc fold+split, w split, proj split, inits — one launch.     */
/* grid 1176, 256 thr.                                                 */
/* ------------------------------------------------------------------ */
__global__ void k_misc(const float* __restrict__ wq, const float* __restrict__ wk,
                       const float* __restrict__ wv, const float* __restrict__ proj,
                       const float* __restrict__ wo, const float* __restrict__ bo,
                       const float* __restrict__ wp, const float* __restrict__ bp){
    __shared__ float row[256];
    int bid = blockIdx.x, t = threadIdx.x;
    if (bid < 256){
        int o2 = bid;
        float s = 0.f;
        for (int o = 0; o < 256; o++) s += wp[o2*256 + o] * wo[o*256 + t];
        row[t] = s;
        if (t == 0){
            float sb = 0.f;
            for (int o = 0; o < 256; o++) sb += wp[o2*256 + o] * bo[o];
            g_bc[o2] = sb + bp[o2];
        }
        __syncthreads();
        if (t < 128){
            u32 h, l;
            f16split2(row[2*t], row[2*t + 1], h, l);
            g_wch[o2*128 + t] = h;
            g_wcl[o2*128 + t] = l;
        }
    } else if (bid < 640){
        int i = (bid - 256)*256 + t;
        int oc = i >> 15, rem = i & 32767;
        int r = rem >> 7, p = rem & 127;
        const float* W = (oc == 0) ? wq : (oc == 1 ? wk : wv);
        u32 h, l;
        f16split2(W[r*256 + p*2], W[r*256 + p*2 + 1], h, l);
        g_wh[i] = h; g_wl[i] = l;
    } else if (bid < 648){
        int i = (bid - 640)*256 + t;
        int m = i >> 4, p = i & 15;
        u32 h, l;
        f16split2(proj[m*32 + p*2]*NRM, proj[m*32 + p*2 + 1]*NRM, h, l);
        g_projh[i] = h; g_projl[i] = l;
        if (bid == 640 && t < 32) g_kmax[t] = -1e30f;
    } else {
        int i = (bid - 648)*256 + t;
        if (i < 32*MF*33) g_ctx[i] = 0.f;
    }
}

__global__ void k_ctx_cvt(){
    int bh = blockIdx.x, t = threadIdx.x;
    for (int i = t; i < 4096; i += 256){
        int j = i >> 6, mp = i & 63;
        float a = 0.f, b = 0.f;
        if (j < 33){
            a = g_ctx[((size_t)bh*MF + mp*2)*33 + j];
            b = g_ctx[((size_t)bh*MF + mp*2 + 1)*33 + j];
        }
        u32 h, l;
        f16split2(a, b, h, l);
        g_ctxh2[bh*4096 + i] = h;
        g_ctxl2[bh*4096 + i] = l;
    }
}

/* ------------------------------------------------------------------ */
/* K_xcvt: transpose+split x -> g_xh/g_xl [token][128 pairs]           */
/* ------------------------------------------------------------------ */
__global__ void __launch_bounds__(256) k_xcvt(const float* __restrict__ x){
    __shared__ u32 sh[128*33];
    __shared__ u32 sl[128*33];
    int tid = threadIdx.x, wid = tid >> 5, lane = tid & 31;
    int t0 = blockIdx.x * 128;
    int b = t0 / NN, tl0 = t0 % NN;
    int tq = lane * 4, cg2 = wid * 2;

    for (int ch = 0; ch < 4; ch++){
        int c0 = ch * 64;
#pragma unroll
        for (int u = 0; u < 4; u++){
            int cl = u*16 + cg2;
            const float* p = &x[((size_t)(b*256 + c0 + cl))*NN + tl0 + tq];
            float4 f0 = *(const float4*)p;
            float4 f1 = *(const float4*)(p + NN);
            const float* e0 = (const float*)&f0;
            const float* e1 = (const float*)&f1;
#pragma unroll
            for (int j = 0; j < 4; j++){
                u32 h, l;
                f16split2(e0[j], e1[j], h, l);
                sh[(tq + j)*33 + (cl >> 1)] = h;
                sl[(tq + j)*33 + (cl >> 1)] = l;
            }
        }
        __syncthreads();
#pragma unroll
        for (int r = 0; r < 16; r++){
            int i = r*256 + tid;
            int row = i >> 5, p = i & 31;
            size_t g = (size_t)(t0 + row)*128 + ch*32 + p;
            g_xh[g] = sh[row*33 + p];
            g_xl[g] = sl[row*33 + p];
        }
        __syncthreads();
    }
}

/* ------------------------------------------------------------------ */
/* big-tile mma body: 3-pass (qkv)                                     */
/* ------------------------------------------------------------------ */
__device__ __forceinline__ void mma_chunk2(u32 base, int wm, int wn, int lane,
                                           float c[4][4][4]){
    u32 a_off = (u32)((wm + (lane & 15))*PITCHB + (lane >> 4)*16);
    u32 b_off = (u32)((wn + (lane & 7) + ((lane >> 4) & 1)*8)*PITCHB
                      + ((lane >> 3) & 1)*16);
#pragma unroll
    for (int ks = 0; ks < 4; ks++){
        u32 ah[4][4], al[4][4], bh[2][4];
#pragma unroll
        for (int mt = 0; mt < 4; mt++)
            LDM4(ah[mt], base + S2A_H + a_off + mt*(16*PITCHB) + ks*32);
#pragma unroll
        for (int np = 0; np < 2; np++)
            LDM4(bh[np], base + S2B_H + b_off + np*(16*PITCHB) + ks*32);
#pragma unroll
        for (int mt = 0; mt < 4; mt++)
            LDM4(al[mt], base + S2A_L + a_off + mt*(16*PITCHB) + ks*32);
#pragma unroll
        for (int mt = 0; mt < 4; mt++)
#pragma unroll
            for (int nt = 0; nt < 4; nt++)
                MMA16816(c[mt][nt], ah[mt], bh[nt>>1][(nt&1)*2], bh[nt>>1][(nt&1)*2+1]);
#pragma unroll
        for (int mt = 0; mt < 4; mt++)
#pragma unroll
            for (int nt = 0; nt < 4; nt++)
                MMA16816(c[mt][nt], al[mt], bh[nt>>1][(nt&1)*2], bh[nt>>1][(nt&1)*2+1]);
        {
            u32 bl[2][4];
#pragma unroll
            for (int np = 0; np < 2; np++)
                LDM4(bl[np], base + S2B_L + b_off + np*(16*PITCHB) + ks*32);
#pragma unroll
            for (int mt = 0; mt < 4; mt++)
#pragma unroll
                for (int nt = 0; nt < 4; nt++)
                    MMA16816(c[mt][nt], ah[mt], bl[nt>>1][(nt&1)*2], bl[nt>>1][(nt&1)*2+1]);
        }
    }
}

/* 2-pass variant for final (A hi only): AhBh + AhBl                   */
__device__ __forceinline__ void mma_chunk2f(u32 base, int wm, int wn, int lane,
                                            float c[4][4][4]){
    u32 a_off = (u32)((wm + (lane & 15))*PITCHB + (lane >> 4)*16);
    u32 b_off = (u32)((wn + (lane & 7) + ((lane >> 4) & 1)*8)*PITCHB
                      + ((lane >> 3) & 1)*16);
#pragma unroll
    for (int ks = 0; ks < 4; ks++){
        u32 ah[4][4], bh[2][4], bl[2][4];
#pragma unroll
        for (int mt = 0; mt < 4; mt++)
            LDM4(ah[mt], base + S2A_H + a_off + mt*(16*PITCHB) + ks*32);
#pragma unroll
        for (int np = 0; np < 2; np++)
            LDM4(bh[np], base + S2B_H + b_off + np*(16*PITCHB) + ks*32);
#pragma unroll
        for (int np = 0; np < 2; np++)
            LDM4(bl[np], base + S2B_L + b_off + np*(16*PITCHB) + ks*32);
#pragma unroll
        for (int mt = 0; mt < 4; mt++)
#pragma unroll
            for (int nt = 0; nt < 4; nt++)
                MMA16816(c[mt][nt], ah[mt], bh[nt>>1][(nt&1)*2], bh[nt>>1][(nt&1)*2+1]);
#pragma unroll
        for (int mt = 0; mt < 4; mt++)
#pragma unroll
            for (int nt = 0; nt < 4; nt++)
                MMA16816(c[mt][nt], ah[mt], bl[nt>>1][(nt&1)*2], bl[nt>>1][(nt&1)*2+1]);
    }
}

__device__ __forceinline__ void copy_chunk2(u32 base, int tid, int ch,
        const u32* pah, const u32* pal, const u32* pbh, const u32* pbl){
#pragma unroll
    for (int it = 0; it < 4; it++){
        int i = it*512 + tid;
        int row = i >> 3, pg = (i & 7)*4;
        size_t ga = (size_t)row*128 + ch*32 + pg;
        u32 off = base + (u32)(row*PITCHB + pg*4);
        CPA16(off + S2A_H, pah + ga);
        CPA16(off + S2A_L, pal + ga);
    }
#pragma unroll
    for (int it = 0; it < 2; it++){
        int i = it*512 + tid;
        int row = i >> 3, pg = (i & 7)*4;
        size_t gb = (size_t)row*128 + ch*32 + pg;
        u32 off = base + (u32)(row*PITCHB + pg*4);
        CPA16(off + S2B_H, pbh + gb);
        CPA16(off + S2B_L, pbl + gb);
    }
}

/* A-hi-only copy for final */
__device__ __forceinline__ void copy_chunk2f(u32 base, int tid, int ch,
        const u32* pah, const u32* pbh, const u32* pbl){
#pragma unroll
    for (int it = 0; it < 4; it++){
        int i = it*512 + tid;
        int row = i >> 3, pg = (i & 7)*4;
        size_t ga = (size_t)row*128 + ch*32 + pg;
        u32 off = base + (u32)(row*PITCHB + pg*4);
        CPA16(off + S2A_H, pah + ga);
    }
#pragma unroll
    for (int it = 0; it < 2; it++){
        int i = it*512 + tid;
        int row = i >> 3, pg = (i & 7)*4;
        size_t gb = (size_t)row*128 + ch*32 + pg;
        u32 off = base + (u32)(row*PITCHB + pg*4);
        CPA16(off + S2B_H, pbh + gb);
        CPA16(off + S2B_L, pbl + gb);
    }
}

__device__ __forceinline__ void gemm_pipe2(u32 smb, int tid, int wm, int wn, int lane,
        const u32* pah, const u32* pal, const u32* pbh, const u32* pbl,
        float c[4][4][4]){
    copy_chunk2(smb,        tid, 0, pah, pal, pbh, pbl);
    CP_COMMIT();
    copy_chunk2(smb + BUF2, tid, 1, pah, pal, pbh, pbl);
    CP_COMMIT();
#pragma unroll
    for (int ch = 0; ch < 4; ch++){
        if (ch < 3) CP_WAIT1(); else CP_WAIT0();
        __syncthreads();
        mma_chunk2(smb + (ch & 1)*BUF2, wm, wn, lane, c);
        __syncthreads();
        if (ch < 2){
            copy_chunk2(smb + (ch & 1)*BUF2, tid, ch + 2, pah, pal, pbh, pbl);
            CP_COMMIT();
        }
    }
}

__device__ __forceinline__ void gemm_pipe2f(u32 smb, int tid, int wm, int wn, int lane,
        const u32* pah, const u32* pbh, const u32* pbl,
        float c[4][4][4]){
    copy_chunk2f(smb,        tid, 0, pah, pbh, pbl);
    CP_COMMIT();
    copy_chunk2f(smb + BUF2, tid, 1, pah, pbh, pbl);
    CP_COMMIT();
#pragma unroll
    for (int ch = 0; ch < 4; ch++){
        if (ch < 3) CP_WAIT1(); else CP_WAIT0();
        __syncthreads();
        mma_chunk2f(smb + (ch & 1)*BUF2, wm, wn, lane, c);
        __syncthreads();
        if (ch < 2){
            copy_chunk2f(smb + (ch & 1)*BUF2, tid, ch + 2, pah, pbh, pbl);
            CP_COMMIT();
        }
    }
}

/* ------------------------------------------------------------------ */
/* K1: QKV GEMM — 256x128 tile, 512 thr, double-buffered, 3-pass.      */
/* ------------------------------------------------------------------ */
__global__ void __launch_bounds__(512, 1) k_qkv_t(){
    extern __shared__ char sm[];
    u32 smb = smem_u32(sm);
    int tid = threadIdx.x, wid = tid >> 5, lane = tid & 31;
    int oc = blockIdx.x;
    int t0 = blockIdx.y * 256;
    int wsel = oc >> 1;
    u32* dsth = (oc < 2) ? g_qh : (oc < 4 ? g_kh : g_vh);
    u32* dstl = (oc < 2) ? g_ql : (oc < 4 ? g_kl : g_vl);
    int or0 = (oc & 1) * 128;

    const u32* pah = g_xh + (size_t)t0*128;
    const u32* pal = g_xl + (size_t)t0*128;
    const u32* pbh = g_wh + (size_t)wsel*32768 + (size_t)or0*128;
    const u32* pbl = g_wl + (size_t)wsel*32768 + (size_t)or0*128;

    int wm = (wid >> 2) * 64, wn = (wid & 3) * 32;

    float c[4][4][4];
#pragma unroll
    for (int mt = 0; mt < 4; mt++)
#pragma unroll
        for (int nt = 0; nt < 4; nt++)
#pragma unroll
            for (int r = 0; r < 4; r++) c[mt][nt][r] = 0.f;

    gemm_pipe2(smb, tid, wm, wn, lane, pah, pal, pbh, pbl, c);

    u32* SH = (u32*)sm;
    u32* SL = (u32*)(sm + 69632);
#pragma unroll
    for (int mt = 0; mt < 4; mt++){
#pragma unroll
        for (int nt = 0; nt < 4; nt++){
            int r = wm + mt*16 + (lane >> 2);
            int cp = (wn + nt*8 + (lane & 3)*2) >> 1;
            u32 h, l;
            f16split2(c[mt][nt][0], c[mt][nt][1], h, l);
            SH[r*68 + cp] = h; SL[r*68 + cp] = l;
            f16split2(c[mt][nt][2], c[mt][nt][3], h, l);
            SH[(r+8)*68 + cp] = h; SL[(r+8)*68 + cp] = l;
        }
    }
    __syncthreads();
#pragma unroll
    for (int it = 0; it < 8; it++){
        int i = it*512 + tid;
        int row = i >> 4, c4 = (i & 15)*4;
        size_t g = (size_t)(t0 + row)*128 + (or0 >> 1) + c4;
        *(uint4*)&dsth[g] = *(uint4*)&SH[row*68 + c4];
        *(uint4*)&dstl[g] = *(uint4*)&SL[row*68 + c4];
    }
}

/* ------------------------------------------------------------------ */
/* K5: final GEMM — 256x128 tile, 512 thr, 2-pass (A hi only).         */
/* ------------------------------------------------------------------ */
__global__ void __launch_bounds__(512, 1) k_final_t(float* __restrict__ out){
    extern __shared__ char sm[];
    u32 smb = smem_u32(sm);
    int tid = threadIdx.x, wid = tid >> 5, lane = tid & 31;
    int o0 = blockIdx.x * 128;
    int t0 = blockIdx.y * 256;
    int b = t0 / NN, tl0 = t0 % NN;

    const u32* pah = g_ah + (size_t)t0*128;
    const u32* pbh = g_wch + (size_t)o0*128;
    const u32* pbl = g_wcl + (size_t)o0*128;

    int wm = (wid >> 2) * 64, wn = (wid & 3) * 32;

    float c[4][4][4];
#pragma unroll
    for (int mt = 0; mt < 4; mt++)
#pragma unroll
        for (int nt = 0; nt < 4; nt++)
#pragma unroll
            for (int r = 0; r < 4; r++) c[mt][nt][r] = 0.f;

    gemm_pipe2f(smb, tid, wm, wn, lane, pah, pbh, pbl, c);

    float* stage = (float*)sm;
#pragma unroll
    for (int mt = 0; mt < 4; mt++){
#pragma unroll
        for (int nt = 0; nt < 4; nt++){
            int r = wm + mt*16 + (lane >> 2);
            int cc = wn + nt*8 + (lane & 3)*2;
            stage[cc*260 + r]         = c[mt][nt][0];
            stage[(cc+1)*260 + r]     = c[mt][nt][1];
            stage[cc*260 + r + 8]     = c[mt][nt][2];
            stage[(cc+1)*260 + r + 8] = c[mt][nt][3];
        }
    }
    __syncthreads();
#pragma unroll
    for (int i2 = 0; i2 < 16; i2++){
        int idx = i2*512 + tid;
        int cc = idx >> 6, t4 = (idx & 63) * 4;
        int o = o0 + cc;
        float bias = g_bc[o];
        float4 v = *(float4*)&stage[cc*260 + t4];
        v.x += bias; v.y += bias; v.z += bias; v.w += bias;
        *(float4*)&out[((size_t)b*256 + o)*NN + tl0 + t4] = v;
    }
}

/* ------------------------------------------------------------------ */
/* K2: key-dash max — 2 tiles of 128 tokens per block. grid (36, 32).  */
/* ------------------------------------------------------------------ */
__global__ void __launch_bounds__(256) k_kmax(){
    __shared__ u32 projh[128*20];
    __shared__ u32 projl[128*20];
    __shared__ u32 kth[128*20];
    __shared__ u32 ktl[128*20];
    __shared__ float red[256];
    int bh = blockIdx.y, b = bh >> 3, h = bh & 7;
    int t = threadIdx.x, wid = t >> 5, lane = t & 31;

#pragma unroll
    for (int r = 0; r < 2; r++){
        int i = r*256 + t;
        int m = i >> 2, q4 = (i & 3)*4;
        *(uint4*)&projh[m*20 + q4] = *(const uint4*)&g_projh[m*16 + q4];
        *(uint4*)&projl[m*20 + q4] = *(const uint4*)&g_projl[m*16 + q4];
    }

    int wm = (wid >> 1)*32, wn = (wid & 1)*64;
    u32 smPH = smem_u32(projh), smPL = smem_u32(projl);
    u32 smKH = smem_u32(kth),   smKL = smem_u32(ktl);
    u32 a_off = (u32)((wm + (lane & 15))*80 + (lane >> 4)*16);
    u32 b_off = (u32)((wn + (lane & 7) + ((lane >> 4) & 1)*8)*80 + ((lane >> 3) & 1)*16);

    float mx = -1e30f;
    for (int tile = 0; tile < 2; tile++){
        int n0 = blockIdx.x * 256 + tile * 128;
#pragma unroll
        for (int r = 0; r < 2; r++){
            int i = r*256 + t;
            int m = i >> 2, q4 = (i & 3)*4;
            size_t g = (size_t)(b*NN + n0 + m)*128 + h*16 + q4;
            *(uint4*)&kth[m*20 + q4] = *(const uint4*)&g_kh[g];
            *(uint4*)&ktl[m*20 + q4] = *(const uint4*)&g_kl[g];
        }
        __syncthreads();

        float c[2][8][4];
#pragma unroll
        for (int mt = 0; mt < 2; mt++)
#pragma unroll
            for (int nt = 0; nt < 8; nt++)
#pragma unroll
                for (int r = 0; r < 4; r++) c[mt][nt][r] = 0.f;
#pragma unroll
        for (int ks = 0; ks < 2; ks++){
            u32 ah[2][4], al[2][4], bh2[4][4];
#pragma unroll
            for (int mt = 0; mt < 2; mt++)
                LDM4(ah[mt], smPH + a_off + mt*(16*80) + ks*32);
#pragma unroll
            for (int np = 0; np < 4; np++)
                LDM4(bh2[np], smKH + b_off + np*(16*80) + ks*32);
#pragma unroll
            for (int mt = 0; mt < 2; mt++)
                LDM4(al[mt], smPL + a_off + mt*(16*80) + ks*32);
#pragma unroll
            for (int mt = 0; mt < 2; mt++)
#pragma unroll
                for (int nt = 0; nt < 8; nt++)
                    MMA16816(c[mt][nt], ah[mt], bh2[nt>>1][(nt&1)*2], bh2[nt>>1][(nt&1)*2+1]);
#pragma unroll
            for (int mt = 0; mt < 2; mt++)
#pragma unroll
                for (int nt = 0; nt < 8; nt++)
                    MMA16816(c[mt][nt], al[mt], bh2[nt>>1][(nt&1)*2], bh2[nt>>1][(nt&1)*2+1]);
            {
                u32 bl[4][4];
#pragma unroll
                for (int np = 0; np < 4; np++)
                    LDM4(bl[np], smKL + b_off + np*(16*80) + ks*32);
#pragma unroll
                for (int mt = 0; mt < 2; mt++)
#pragma unroll
                    for (int nt = 0; nt < 8; nt++)
                        MMA16816(c[mt][nt], ah[mt], bl[nt>>1][(nt&1)*2], bl[nt>>1][(nt&1)*2+1]);
            }
        }
#pragma unroll
        for (int mt = 0; mt < 2; mt++)
#pragma unroll
            for (int nt = 0; nt < 8; nt++)
#pragma unroll
                for (int r = 0; r < 4; r++) mx = fmaxf(mx, c[mt][nt][r]);
        __syncthreads();
    }
    red[t] = mx;
    __syncthreads();
    for (int s = 128; s > 0; s >>= 1){
        if (t < (unsigned)s) red[t] = fmaxf(red[t], red[t + s]);
        __syncthreads();
    }
    if (t == 0) atomicMaxF(&g_kmax[bh], red[0]);
}

/* ------------------------------------------------------------------ */
/* K3: fused key features + ctx. grid (9, 32) — one full wave.         */
/* ------------------------------------------------------------------ */
#define CP_PROJH 0
#define CP_PROJL 10240
#define CP_KTH   20480
#define CP_KTL   25600
#define CP_KPSH  30720
#define CP_KPSL  49152
#define CP_VTH   67584
#define CP_VTL   74752
#define CP_DIAG  81920
#define CTX_SMEM 82176
#define CTX_SPLITS 9
#define CTX_TILES  16

__global__ void __launch_bounds__(256) k_ctx2(){
    extern __shared__ char sm[];
    u32 smb = smem_u32(sm);
    int bh = blockIdx.y, b = bh >> 3, h = bh & 7;
    int sp = blockIdx.x;
    int t = threadIdx.x, wid = t >> 5, lane = t & 31;
    float gmax = g_kmax[bh];

    u32* PJH = (u32*)(sm + CP_PROJH); u32* PJL = (u32*)(sm + CP_PROJL);
    u32* KTH = (u32*)(sm + CP_KTH);   u32* KTL = (u32*)(sm + CP_KTL);
    u32* VTH = (u32*)(sm + CP_VTH);   u32* VTL = (u32*)(sm + CP_VTL);
    float* DIAG = (float*)(sm + CP_DIAG);

#pragma unroll
    for (int r = 0; r < 2; r++){
        int i = r*256 + t;
        int m = i >> 2, q4 = (i & 3)*4;
        *(uint4*)&PJH[m*20 + q4] = *(const uint4*)&g_projh[m*16 + q4];
        *(uint4*)&PJL[m*20 + q4] = *(const uint4*)&g_projl[m*16 + q4];
    }
    for (int i = t; i < 1536; i += 256){
        int mat = (i >= 768), rem = (i >= 768) ? i - 768 : i;
        int tok = rem / 12, cc = 16 + rem % 12;
        u32 v = (mat == 0 && cc == 16) ? 0x00003C00u : 0u;
        ((mat == 0) ? VTH : VTL)[tok*28 + cc] = v;
    }

    int wm1 = (wid >> 1)*32, wn1 = (wid & 1)*32;
    u32 a1_off = (u32)((wm1 + (lane & 15))*80 + (lane >> 4)*16);
    u32 b1_off = (u32)((wn1 + (lane & 7) + ((lane >> 4) & 1)*8)*80 + ((lane >> 3) & 1)*16);
    int wm2 = (wid >> 1)*32, wn2 = (wid & 1)*24;
    u32 a2_off = (u32)((wm2 + (lane & 15))*144 + (lane >> 4)*16);
    u32 b2row = (u32)(((lane & 7) + ((lane >> 3) & 1)*8)*112);
    u32 b2col0 = (u32)((wn2 + ((lane >> 4) & 1)*8)*2);

    float c2[2][3][4];
#pragma unroll
    for (int mt = 0; mt < 2; mt++)
#pragma unroll
        for (int nt = 0; nt < 3; nt++)
#pragma unroll
            for (int r = 0; r < 4; r++) c2[mt][nt][r] = 0.f;

    for (int it = 0; it < CTX_TILES; it++){
        int n0 = sp*(CTX_TILES*64) + it*64;
        {
            int tok = t >> 2, q4 = (t & 3)*4;
            size_t g = (size_t)(b*NN + n0 + tok)*128 + h*16 + q4;
            *(uint4*)&KTH[tok*20 + q4] = *(const uint4*)&g_kh[g];
            *(uint4*)&KTL[tok*20 + q4] = *(const uint4*)&g_kl[g];
            *(uint4*)&VTH[tok*28 + q4] = *(const uint4*)&g_vh[g];
            *(uint4*)&VTL[tok*28 + q4] = *(const uint4*)&g_vl[g];
        }
        __syncthreads();
        if (t < 64){
            float sq = 0.f;
#pragma unroll
            for (int i = 0; i < 16; i++){
                float2 v = h2f(KTH[t*20 + i], KTL[t*20 + i]);
                sq += v.x*v.x + v.y*v.y;
            }
            DIAG[t] = HALF_NRM2 * sq;
        }
        __syncthreads();

        float c1[2][4][4];
#pragma unroll
        for (int mt = 0; mt < 2; mt++)
#pragma unroll
            for (int nt = 0; nt < 4; nt++)
#pragma unroll
                for (int r = 0; r < 4; r++) c1[mt][nt][r] = 0.f;
#pragma unroll
        for (int ks = 0; ks < 2; ks++){
            u32 ah[2][4], al[2][4], bhh[2][4];
#pragma unroll
            for (int mt = 0; mt < 2; mt++)
                LDM4(ah[mt], smb + CP_PROJH + a1_off + mt*(16*80) + ks*32);
#pragma unroll
            for (int np = 0; np < 2; np++)
                LDM4(bhh[np], smb + CP_KTH + b1_off + np*(16*80) + ks*32);
#pragma unroll
            for (int mt = 0; mt < 2; mt++)
                LDM4(al[mt], smb + CP_PROJL + a1_off + mt*(16*80) + ks*32);
#pragma unroll
            for (int mt = 0; mt < 2; mt++)
#pragma unroll
                for (int nt = 0; nt < 4; nt++)
                    MMA16816(c1[mt][nt], ah[mt], bhh[nt>>1][(nt&1)*2], bhh[nt>>1][(nt&1)*2+1]);
#pragma unroll
            for (int mt = 0; mt < 2; mt++)
#pragma unroll
                for (int nt = 0; nt < 4; nt++)
                    MMA16816(c1[mt][nt], al[mt], bhh[nt>>1][(nt&1)*2], bhh[nt>>1][(nt&1)*2+1]);
            {
                u32 bl[2][4];
#pragma unroll
                for (int np = 0; np < 2; np++)
                    LDM4(bl[np], smb + CP_KTL + b1_off + np*(16*80) + ks*32);
#pragma unroll
                for (int mt = 0; mt < 2; mt++)
#pragma unroll
                    for (int nt = 0; nt < 4; nt++)
                        MMA16816(c1[mt][nt], ah[mt], bl[nt>>1][(nt&1)*2], bl[nt>>1][(nt&1)*2+1]);
            }
        }
        u32* KPH = (u32*)(sm + CP_KPSH);
        u32* KPL = (u32*)(sm + CP_KPSL);
#pragma unroll
        for (int mt = 0; mt < 2; mt++){
#pragma unroll
            for (int nt = 0; nt < 4; nt++){
                int col = wn1 + nt*8 + (lane & 3)*2;
                float d0 = DIAG[col] + gmax, d1 = DIAG[col+1] + gmax;
                int r0 = wm1 + mt*16 + (lane >> 2);
                float v0 = KP_RATIO*(__expf(c1[mt][nt][0] - d0) + EPSF);
                float v1 = KP_RATIO*(__expf(c1[mt][nt][1] - d1) + EPSF);
                float v2 = KP_RATIO*(__expf(c1[mt][nt][2] - d0) + EPSF);
                float v3 = KP_RATIO*(__expf(c1[mt][nt][3] - d1) + EPSF);
                u32 hh, ll;
                f16split2(v0, v1, hh, ll);
                KPH[r0*36 + (col>>1)] = hh; KPL[r0*36 + (col>>1)] = ll;
                f16split2(v2, v3, hh, ll);
                KPH[(r0+8)*36 + (col>>1)] = hh; KPL[(r0+8)*36 + (col>>1)] = ll;
            }
        }
        __syncthreads();

#pragma unroll
        for (int ks = 0; ks < 4; ks++){
            u32 ah[2][4], al[2][4], bhh[2][4];
            u32 rb = (u32)(ks*16*112) + b2row;
#pragma unroll
            for (int mt = 0; mt < 2; mt++)
                LDM4(ah[mt], smb + CP_KPSH + a2_off + mt*(16*144) + ks*32);
#pragma unroll
            for (int np = 0; np < 2; np++)
                LDM4T(bhh[np], smb + CP_VTH + rb + b2col0 + np*32);
#pragma unroll
            for (int mt = 0; mt < 2; mt++)
                LDM4(al[mt], smb + CP_KPSL + a2_off + mt*(16*144) + ks*32);
#pragma unroll
            for (int mt = 0; mt < 2; mt++)
#pragma unroll
                for (int nt = 0; nt < 3; nt++)
                    MMA16816(c2[mt][nt], ah[mt], bhh[nt>>1][(nt&1)*2], bhh[nt>>1][(nt&1)*2+1]);
#pragma unroll
            for (int mt = 0; mt < 2; mt++)
#pragma unroll
                for (int nt = 0; nt < 3; nt++)
                    MMA16816(c2[mt][nt], al[mt], bhh[nt>>1][(nt&1)*2], bhh[nt>>1][(nt&1)*2+1]);
            {
                u32 bl[2][4];
#pragma unroll
                for (int np = 0; np < 2; np++)
                    LDM4T(bl[np], smb + CP_VTL + rb + b2col0 + np*32);
#pragma unroll
                for (int mt = 0; mt < 2; mt++)
#pragma unroll
                    for (int nt = 0; nt < 3; nt++)
                        MMA16816(c2[mt][nt], ah[mt], bl[nt>>1][(nt&1)*2], bl[nt>>1][(nt&1)*2+1]);
            }
        }
        __syncthreads();
    }

#pragma unroll
    for (int mt = 0; mt < 2; mt++){
#pragma unroll
        for (int nt = 0; nt < 3; nt++){
            int m = wm2 + mt*16 + (lane >> 2);
            int n = wn2 + nt*8 + (lane & 3)*2;
            size_t base = ((size_t)bh*MF + m)*33;
            if (n < 33)   atomicAdd(&g_ctx[base + n],     c2[mt][nt][0]);
            if (n+1 < 33) atomicAdd(&g_ctx[base + n + 1], c2[mt][nt][1]);
            if (n < 33)   atomicAdd(&g_ctx[base + 264 + n],     c2[mt][nt][2]);
            if (n+1 < 33) atomicAdd(&g_ctx[base + 264 + n + 1], c2[mt][nt][3]);
        }
    }
}

/* ------------------------------------------------------------------ */
/* K4: fused query features + qp@ctx + d_inv. 2 tiles/block (R13).     */
/* grid (72, 32), 256 thr.                                             */
/* ------------------------------------------------------------------ */
#define QP_PROJH 0
#define QP_PROJL 10240
#define QP_QTH   20480
#define QP_QTL   25600
#define QP_QPSH  30720
#define QP_QPSL  49152
#define QP_CTH   67584
#define QP_CTL   84992
#define QP_PM    102400
#define QP_RMAX  103424
#define QP_DIAG  103680
#define QP_STG   QP_QPSH
#define QA_SMEM  103936

__global__ void __launch_bounds__(256) k_qattn2(){
    extern __shared__ char sm[];
    u32 smb = smem_u32(sm);
    int bh = blockIdx.y, b = bh >> 3, h = bh & 7;
    int t = threadIdx.x, wid = t >> 5, lane = t & 31;

    u32* PJH = (u32*)(sm + QP_PROJH); u32* PJL = (u32*)(sm + QP_PROJL);
    u32* QTH = (u32*)(sm + QP_QTH);   u32* QTL = (u32*)(sm + QP_QTL);
    u32* CTH = (u32*)(sm + QP_CTH);   u32* CTL = (u32*)(sm + QP_CTL);
    float* PM = (float*)(sm + QP_PM);
    float* RMAX = (float*)(sm + QP_RMAX);
    float* DIAG = (float*)(sm + QP_DIAG);

#pragma unroll
    for (int r = 0; r < 2; r++){
        int i = r*256 + t;
        int m = i >> 2, q4 = (i & 3)*4;
        *(uint4*)&PJH[m*20 + q4] = *(const uint4*)&g_projh[m*16 + q4];
        *(uint4*)&PJL[m*20 + q4] = *(const uint4*)&g_projl[m*16 + q4];
    }
#pragma unroll
    for (int r = 0; r < 4; r++){
        int i = r*256 + t;
        int j = i >> 4, q4 = (i & 15)*4;
        *(uint4*)&CTH[j*68 + q4] = *(const uint4*)&g_ctxh2[bh*4096 + j*64 + q4];
        *(uint4*)&CTL[j*68 + q4] = *(const uint4*)&g_ctxl2[bh*4096 + j*64 + q4];
    }

    int wm1 = (wid >> 1)*32, wn1 = (wid & 1)*32;
    u32 a1_off = (u32)((wm1 + (lane & 15))*80 + (lane >> 4)*16);
    u32 b1_off = (u32)((wn1 + (lane & 7) + ((lane >> 4) & 1)*8)*80 + ((lane >> 3) & 1)*16);
    int wm2 = (wid >> 1)*16, wn2 = (wid & 1)*32;
    u32 a2_off = (u32)((wm2 + (lane & 15))*272 + (lane >> 4)*16);

    for (int tile = 0; tile < 2; tile++){
        int n0 = blockIdx.x * 128 + tile * 64;
        {
            int tok = t >> 2, q4 = (t & 3)*4;
            size_t g = (size_t)(b*NN + n0 + tok)*128 + h*16 + q4;
            *(uint4*)&QTH[tok*20 + q4] = *(const uint4*)&g_qh[g];
            *(uint4*)&QTL[tok*20 + q4] = *(const uint4*)&g_ql[g];
        }
        __syncthreads();
        if (t < 64){
            float sq = 0.f;
#pragma unroll
            for (int i = 0; i < 16; i++){
                float2 v = h2f(QTH[t*20 + i], QTL[t*20 + i]);
                sq += v.x*v.x + v.y*v.y;
            }
            DIAG[t] = HALF_NRM2 * sq;
        }
        __syncthreads();

        float c1[2][4][4];
#pragma unroll
        for (int mt = 0; mt < 2; mt++)
#pragma unroll
            for (int nt = 0; nt < 4; nt++)
#pragma unroll
                for (int r = 0; r < 4; r++) c1[mt][nt][r] = 0.f;
#pragma unroll
        for (int ks = 0; ks < 2; ks++){
            u32 ah[2][4], al[2][4], bhh[2][4];
#pragma unroll
            for (int mt = 0; mt < 2; mt++)
                LDM4(ah[mt], smb + QP_PROJH + a1_off + mt*(16*80) + ks*32);
#pragma unroll
            for (int np = 0; np < 2; np++)
                LDM4(bhh[np], smb + QP_QTH + b1_off + np*(16*80) + ks*32);
#pragma unroll
            for (int mt = 0; mt < 2; mt++)
                LDM4(al[mt], smb + QP_PROJL + a1_off + mt*(16*80) + ks*32);
#pragma unroll
            for (int mt = 0; mt < 2; mt++)
#pragma unroll
                for (int nt = 0; nt < 4; nt++)
                    MMA16816(c1[mt][nt], ah[mt], bhh[nt>>1][(nt&1)*2], bhh[nt>>1][(nt&1)*2+1]);
#pragma unroll
            for (int mt = 0; mt < 2; mt++)
#pragma unroll
                for (int nt = 0; nt < 4; nt++)
                    MMA16816(c1[mt][nt], al[mt], bhh[nt>>1][(nt&1)*2], bhh[nt>>1][(nt&1)*2+1]);
            {
                u32 bl[2][4];
#pragma unroll
                for (int np = 0; np < 2; np++)
                    LDM4(bl[np], smb + QP_QTL + b1_off + np*(16*80) + ks*32);
#pragma unroll
                for (int mt = 0; mt < 2; mt++)
#pragma unroll
                    for (int nt = 0; nt < 4; nt++)
                        MMA16816(c1[mt][nt], ah[mt], bl[nt>>1][(nt&1)*2], bl[nt>>1][(nt&1)*2+1]);
            }
        }

#pragma unroll
        for (int nt = 0; nt < 4; nt++){
            float me = fmaxf(fmaxf(c1[0][nt][0], c1[0][nt][2]),
                             fmaxf(c1[1][nt][0], c1[1][nt][2]));
            float mo = fmaxf(fmaxf(c1[0][nt][1], c1[0][nt][3]),
                             fmaxf(c1[1][nt][1], c1[1][nt][3]));
#pragma unroll
            for (int s = 4; s < 32; s <<= 1){
                me = fmaxf(me, __shfl_xor_sync(0xFFFFFFFF, me, s));
                mo = fmaxf(mo, __shfl_xor_sync(0xFFFFFFFF, mo, s));
            }
            if ((lane >> 2) == 0){
                int col = wn1 + nt*8 + (lane & 3)*2;
                PM[(wid >> 1)*64 + col]     = me;
                PM[(wid >> 1)*64 + col + 1] = mo;
            }
        }
        __syncthreads();
        if (t < 64){
            float mx = PM[t];
            mx = fmaxf(mx, PM[64 + t]);
            mx = fmaxf(mx, PM[128 + t]);
            mx = fmaxf(mx, PM[192 + t]);
            RMAX[t] = mx;
        }
        __syncthreads();

        {
            u32* QPH = (u32*)(sm + QP_QPSH);
            u32* QPL = (u32*)(sm + QP_QPSL);
#pragma unroll
            for (int mt = 0; mt < 2; mt++){
#pragma unroll
                for (int nt = 0; nt < 4; nt++){
                    int col = wn1 + nt*8 + (lane & 3)*2;
                    float d0 = DIAG[col] + RMAX[col], d1 = DIAG[col+1] + RMAX[col+1];
                    int r0 = wm1 + mt*16 + (lane >> 2);
                    float v0 = QP_RATIO*(__expf(c1[mt][nt][0] - d0) + EPSF);
                    float v1 = QP_RATIO*(__expf(c1[mt][nt][1] - d1) + EPSF);
                    float v2 = QP_RATIO*(__expf(c1[mt][nt][2] - d0) + EPSF);
                    float v3 = QP_RATIO*(__expf(c1[mt][nt][3] - d1) + EPSF);
                    u32 hh, ll;
                    f16split2(v0, v1, hh, ll);
                    QPH[r0*36 + (col>>1)] = hh; QPL[r0*36 + (col>>1)] = ll;
                    f16split2(v2, v3, hh, ll);
                    QPH[(r0+8)*36 + (col>>1)] = hh; QPL[(r0+8)*36 + (col>>1)] = ll;
                }
            }
        }
        __syncthreads();

        float c2[4][4];
#pragma unroll
        for (int nt = 0; nt < 4; nt++)
#pragma unroll
            for (int r = 0; r < 4; r++) c2[nt][r] = 0.f;
#pragma unroll
        for (int ks = 0; ks < 8; ks++){
            u32 ah[4], al[4], bt[2][4], btl[2][4];
            LDM4(ah, smb + QP_CTH + a2_off + ks*32);
            LDM4(al, smb + QP_CTL + a2_off + ks*32);
            u32 rowb = (u32)((ks*16 + (lane & 7) + ((lane >> 3) & 1)*8)*144);
#pragma unroll
            for (int np = 0; np < 2; np++){
                u32 colb = (u32)((wn2 + np*16 + ((lane >> 4) & 1)*8)*2);
                LDM4T(bt[np],  smb + QP_QPSH + rowb + colb);
                LDM4T(btl[np], smb + QP_QPSL + rowb + colb);
            }
#pragma unroll
            for (int nt = 0; nt < 4; nt++){
                MMA16816(c2[nt], ah, bt[nt>>1][(nt&1)*2],  bt[nt>>1][(nt&1)*2+1]);
                MMA16816(c2[nt], ah, btl[nt>>1][(nt&1)*2], btl[nt>>1][(nt&1)*2+1]);
                MMA16816(c2[nt], al, bt[nt>>1][(nt&1)*2],  bt[nt>>1][(nt&1)*2+1]);
            }
        }
        __syncthreads();

        float* STG = (float*)(sm + QP_STG);
#pragma unroll
        for (int nt = 0; nt < 4; nt++){
            int j = wm2 + (lane >> 2);
            int tok = wn2 + nt*8 + (lane & 3)*2;
            if (j <= 32){
                STG[j*68 + tok]     = c2[nt][0];
                STG[j*68 + tok + 1] = c2[nt][1];
            }
            if (j + 8 <= 32){
                STG[(j+8)*68 + tok]     = c2[nt][2];
                STG[(j+8)*68 + tok + 1] = c2[nt][3];
            }
        }
        __syncthreads();

        {
            int tok = t >> 2, jb = (t & 3)*8;
            float inv = 1.0f / STG[32*68 + tok];
            u32 hv[4], lv[4];
#pragma unroll
            for (int p = 0; p < 4; p++){
                float v0 = STG[(jb + 2*p)*68 + tok] * inv;
                float v1 = STG[(jb + 2*p + 1)*68 + tok] * inv;
                f16split2(v0, v1, hv[p], lv[p]);
            }
            size_t base = (size_t)(b*NN + n0 + tok)*128 + h*16 + (jb >> 1);
            *(uint4*)&g_ah[base] = make_uint4(hv[0], hv[1], hv[2], hv[3]);
            *(uint4*)&g_al[base] = make_uint4(lv[0], lv[1], lv[2], lv[3]);
        }
        __syncthreads();
    }
}

/* ------------------------------------------------------------------ */
extern "C" void kernel_launch(void* const* d_in, const int* in_sizes, int n_in,
                              void* d_out, int out_size){
    const float* x    = (const float*)d_in[0];
    const float* wq   = (const float*)d_in[1];
    const float* wk   = (const float*)d_in[2];
    const float* wv   = (const float*)d_in[3];
    const float* wo   = (const float*)d_in[4];
    const float* bo   = (const float*)d_in[5];
    const float* proj = (const float*)d_in[6];
    const float* wp   = (const float*)d_in[7];
    const float* bp   = (const float*)d_in[8];
    float* out = (float*)d_out;

    cudaFuncSetAttribute(k_qkv_t,   cudaFuncAttributeMaxDynamicSharedMemorySize, G4_SMEM);
    cudaFuncSetAttribute(k_final_t, cudaFuncAttributeMaxDynamicSharedMemorySize, G4_SMEM);
    cudaFuncSetAttribute(k_ctx2,    cudaFuncAttributeMaxDynamicSharedMemorySize, CTX_SMEM);
    cudaFuncSetAttribute(k_qattn2,  cudaFuncAttributeMaxDynamicSharedMemorySize, QA_SMEM);

    k_misc<<<1176, 256>>>(wq, wk, wv, proj, wo, bo, wp, bp);
    k_xcvt<<<TT/128, 256>>>(x);
    k_qkv_t<<<dim3(6, TT/256), 512, G4_SMEM>>>();
    k_kmax<<<dim3(NN/256, 32), 256>>>();
    k_ctx2<<<dim3(CTX_SPLITS, 32), 256, CTX_SMEM>>>();
    k_ctx_cvt<<<32, 256>>>();
    k_qattn2<<<dim3(NN/128, 32), 256, QA_SMEM>>>();
    k_final_t<<<dim3(2, TT/256), 512, G4_SMEM>>>(out);
}

// round 16
// speedup vs baseline: 1.1090x; 1.0547x over previous
#include <cuda_runtime.h>
#include <cuda_fp16.h>
#include <math.h>

#define BB 4
#define CC 256
#define NHEAD 8
#define DHEAD 32
#define MF 128
#define NN 9216
#define TT (BB*NN)   /* 36864 */

#define NRM       0.4204482076268573f     /* 32^-0.25 */
#define HALF_NRM2 0.08838834764831845f    /* 0.5 * 32^-0.5 */
#define RATIO     0.08838834764831845f    /* 128^-0.5 */
#define EPSF      1e-4f
#define KP_SCALE  64.0f
#define QP_SCALE  64.0f
#define KP_RATIO  (RATIO*KP_SCALE)
#define QP_RATIO  (RATIO*QP_SCALE)

typedef unsigned long long u64;
typedef unsigned int u32;

/* ---------------- mma.sync helpers ---------------- */
__device__ __forceinline__ u32 smem_u32(const void* p){
    u32 a; asm("{ .reg .u64 t; cvta.to.shared.u64 t, %1; cvt.u32.u64 %0, t; }"
               : "=r"(a) : "l"(p)); return a;
}
#define LDM4(r, a) \
    asm volatile("ldmatrix.sync.aligned.m8n8.x4.shared.b16 {%0,%1,%2,%3}, [%4];" \
        : "=r"((r)[0]),"=r"((r)[1]),"=r"((r)[2]),"=r"((r)[3]) : "r"(a))
#define LDM4T(r, a) \
    asm volatile("ldmatrix.sync.aligned.m8n8.x4.trans.shared.b16 {%0,%1,%2,%3}, [%4];" \
        : "=r"((r)[0]),"=r"((r)[1]),"=r"((r)[2]),"=r"((r)[3]) : "r"(a))
#define MMA16816(c, a, b0, b1) \
    asm volatile("mma.sync.aligned.m16n8k16.row.col.f32.f16.f16.f32 " \
        "{%0,%1,%2,%3}, {%4,%5,%6,%7}, {%8,%9}, {%0,%1,%2,%3};" \
        : "+f"((c)[0]),"+f"((c)[1]),"+f"((c)[2]),"+f"((c)[3]) \
        : "r"((a)[0]),"r"((a)[1]),"r"((a)[2]),"r"((a)[3]), "r"(b0),"r"(b1))
#define CPA16(dst, src) \
    asm volatile("cp.async.cg.shared.global [%0], [%1], 16;" :: "r"(dst), "l"(src))
#define CP_COMMIT() asm volatile("cp.async.commit_group;")
#define CP_WAIT0()  asm volatile("cp.async.wait_group 0;")
#define CP_WAIT1()  asm volatile("cp.async.wait_group 1;")

__device__ __forceinline__ void f16split2(float a, float b, u32 &h, u32 &l){
    __half2 hh = __floats2half2_rn(a, b);
    float2 bk = __half22float2(hh);
    __half2 ll = __floats2half2_rn(a - bk.x, b - bk.y);
    h = *(u32*)&hh; l = *(u32*)&ll;
}
__device__ __forceinline__ float2 h2f(u32 h, u32 l){
    float2 a = __half22float2(*(__half2*)&h);
    float2 b = __half22float2(*(__half2*)&l);
    return make_float2(a.x + b.x, a.y + b.y);
}

/* big-tile GEMM smem: per buffer A 256x32h x2 + B 128x32h x2, pitch 144 */
#define PITCHB 144
#define S2A_H 0
#define S2A_L 36864
#define S2B_H 73728
#define S2B_L 92160
#define BUF2  110592
#define G4_SMEM 221184

/* ---------------- scratch ---------------- */
__device__ u32 g_xh[(size_t)TT*128];
__device__ u32 g_xl[(size_t)TT*128];
__device__ u32 g_qh[(size_t)TT*128];
__device__ u32 g_ql[(size_t)TT*128];
__device__ u32 g_kh[(size_t)TT*128];
__device__ u32 g_kl[(size_t)TT*128];
__device__ u32 g_vh[(size_t)TT*128];
__device__ u32 g_vl[(size_t)TT*128];
__device__ u32 g_ah[(size_t)TT*128];
__device__ u32 g_al[(size_t)TT*128];
__device__ u32 g_wh[3*256*128];
__device__ u32 g_wl[3*256*128];
__device__ u32 g_wch[256*128];
__device__ u32 g_wcl[256*128];
__device__ float g_kmax[32];
__device__ float g_ctx[32*MF*33];
__device__ u32 g_ctxh2[32*64*64];
__device__ u32 g_ctxl2[32*64*64];
__device__ float g_bc[CC];
__device__ u32 g_projh[2048];
__device__ u32 g_projl[2048];

__device__ __forceinline__ void atomicMaxF(float* a, float v){
    int old = __float_as_int(*a);
    while (__int_as_float(old) < v){
        int cur = atomicCAS((int*)a, old, __float_as_int(v));
        if (cur == old) break;
        old = cur;
    }
}

/* ------------------------------------------------------------------ */
/* K_misc: Wc fold+split, w split, proj split, inits — one launch.     */
/* ------------------------------------------------------------------ */
__global__ void k_misc(const float* __restrict__ wq, const float* __restrict__ wk,
                       const float* __restrict__ wv, const float* __restrict__ proj,
                       const float* __restrict__ wo, const float* __restrict__ bo,
                       const float* __restrict__ wp, const float* __restrict__ bp){
    __shared__ float row[256];
    int bid = blockIdx.x, t = threadIdx.x;
    if (bid < 256){
        int o2 = bid;
        float s = 0.f;
        for (int o = 0; o < 256; o++) s += wp[o2*256 + o] * wo[o*256 + t];
        row[t] = s;
        if (t == 0){
            float sb = 0.f;
            for (int o = 0; o < 256; o++) sb += wp[o2*256 + o] * bo[o];
            g_bc[o2] = sb + bp[o2];
        }
        __syncthreads();
        if (t < 128){
            u32 h, l;
            f16split2(row[2*t], row[2*t + 1], h, l);
            g_wch[o2*128 + t] = h;
            g_wcl[o2*128 + t] = l;
        }
    } else if (bid < 640){
        int i = (bid - 256)*256 + t;
        int oc = i >> 15, rem = i & 32767;
        int r = rem >> 7, p = rem & 127;
        const float* W = (oc == 0) ? wq : (oc == 1 ? wk : wv);
        u32 h, l;
        f16split2(W[r*256 + p*2], W[r*256 + p*2 + 1], h, l);
        g_wh[i] = h; g_wl[i] = l;
    } else if (bid < 648){
        int i = (bid - 640)*256 + t;
        int m = i >> 4, p = i & 15;
        u32 h, l;
        f16split2(proj[m*32 + p*2]*NRM, proj[m*32 + p*2 + 1]*NRM, h, l);
        g_projh[i] = h; g_projl[i] = l;
        if (bid == 640 && t < 32) g_kmax[t] = -1e30f;
    } else {
        int i = (bid - 648)*256 + t;
        if (i < 32*MF*33) g_ctx[i] = 0.f;
    }
}

__global__ void k_ctx_cvt(){
    int bh = blockIdx.x, t = threadIdx.x;
    for (int i = t; i < 4096; i += 256){
        int j = i >> 6, mp = i & 63;
        float a = 0.f, b = 0.f;
        if (j < 33){
            a = g_ctx[((size_t)bh*MF + mp*2)*33 + j];
            b = g_ctx[((size_t)bh*MF + mp*2 + 1)*33 + j];
        }
        u32 h, l;
        f16split2(a, b, h, l);
        g_ctxh2[bh*4096 + i] = h;
        g_ctxl2[bh*4096 + i] = l;
    }
}

/* ------------------------------------------------------------------ */
/* K_xcvt: transpose+split x -> g_xh/g_xl [token][128 pairs]           */
/* ------------------------------------------------------------------ */
__global__ void __launch_bounds__(256) k_xcvt(const float* __restrict__ x){
    __shared__ u32 sh[128*33];
    __shared__ u32 sl[128*33];
    int tid = threadIdx.x, wid = tid >> 5, lane = tid & 31;
    int t0 = blockIdx.x * 128;
    int b = t0 / NN, tl0 = t0 % NN;
    int tq = lane * 4, cg2 = wid * 2;

    for (int ch = 0; ch < 4; ch++){
        int c0 = ch * 64;
#pragma unroll
        for (int u = 0; u < 4; u++){
            int cl = u*16 + cg2;
            const float* p = &x[((size_t)(b*256 + c0 + cl))*NN + tl0 + tq];
            float4 f0 = *(const float4*)p;
            float4 f1 = *(const float4*)(p + NN);
            const float* e0 = (const float*)&f0;
            const float* e1 = (const float*)&f1;
#pragma unroll
            for (int j = 0; j < 4; j++){
                u32 h, l;
                f16split2(e0[j], e1[j], h, l);
                sh[(tq + j)*33 + (cl >> 1)] = h;
                sl[(tq + j)*33 + (cl >> 1)] = l;
            }
        }
        __syncthreads();
#pragma unroll
        for (int r = 0; r < 16; r++){
            int i = r*256 + tid;
            int row = i >> 5, p = i & 31;
            size_t g = (size_t)(t0 + row)*128 + ch*32 + p;
            g_xh[g] = sh[row*33 + p];
            g_xl[g] = sl[row*33 + p];
        }
        __syncthreads();
    }
}

/* ------------------------------------------------------------------ */
/* big-tile mma body: 3-pass (qkv)                                     */
/* ------------------------------------------------------------------ */
__device__ __forceinline__ void mma_chunk2(u32 base, int wm, int wn, int lane,
                                           float c[4][4][4]){
    u32 a_off = (u32)((wm + (lane & 15))*PITCHB + (lane >> 4)*16);
    u32 b_off = (u32)((wn + (lane & 7) + ((lane >> 4) & 1)*8)*PITCHB
                      + ((lane >> 3) & 1)*16);
#pragma unroll
    for (int ks = 0; ks < 4; ks++){
        u32 ah[4][4], al[4][4], bh[2][4];
#pragma unroll
        for (int mt = 0; mt < 4; mt++)
            LDM4(ah[mt], base + S2A_H + a_off + mt*(16*PITCHB) + ks*32);
#pragma unroll
        for (int np = 0; np < 2; np++)
            LDM4(bh[np], base + S2B_H + b_off + np*(16*PITCHB) + ks*32);
#pragma unroll
        for (int mt = 0; mt < 4; mt++)
            LDM4(al[mt], base + S2A_L + a_off + mt*(16*PITCHB) + ks*32);
#pragma unroll
        for (int mt = 0; mt < 4; mt++)
#pragma unroll
            for (int nt = 0; nt < 4; nt++)
                MMA16816(c[mt][nt], ah[mt], bh[nt>>1][(nt&1)*2], bh[nt>>1][(nt&1)*2+1]);
#pragma unroll
        for (int mt = 0; mt < 4; mt++)
#pragma unroll
            for (int nt = 0; nt < 4; nt++)
                MMA16816(c[mt][nt], al[mt], bh[nt>>1][(nt&1)*2], bh[nt>>1][(nt&1)*2+1]);
        {
            u32 bl[2][4];
#pragma unroll
            for (int np = 0; np < 2; np++)
                LDM4(bl[np], base + S2B_L + b_off + np*(16*PITCHB) + ks*32);
#pragma unroll
            for (int mt = 0; mt < 4; mt++)
#pragma unroll
                for (int nt = 0; nt < 4; nt++)
                    MMA16816(c[mt][nt], ah[mt], bl[nt>>1][(nt&1)*2], bl[nt>>1][(nt&1)*2+1]);
        }
    }
}

/* 2-pass variant for final (A hi only): AhBh + AhBl                   */
__device__ __forceinline__ void mma_chunk2f(u32 base, int wm, int wn, int lane,
                                            float c[4][4][4]){
    u32 a_off = (u32)((wm + (lane & 15))*PITCHB + (lane >> 4)*16);
    u32 b_off = (u32)((wn + (lane & 7) + ((lane >> 4) & 1)*8)*PITCHB
                      + ((lane >> 3) & 1)*16);
#pragma unroll
    for (int ks = 0; ks < 4; ks++){
        u32 ah[4][4], bh[2][4], bl[2][4];
#pragma unroll
        for (int mt = 0; mt < 4; mt++)
            LDM4(ah[mt], base + S2A_H + a_off + mt*(16*PITCHB) + ks*32);
#pragma unroll
        for (int np = 0; np < 2; np++)
            LDM4(bh[np], base + S2B_H + b_off + np*(16*PITCHB) + ks*32);
#pragma unroll
        for (int np = 0; np < 2; np++)
            LDM4(bl[np], base + S2B_L + b_off + np*(16*PITCHB) + ks*32);
#pragma unroll
        for (int mt = 0; mt < 4; mt++)
#pragma unroll
            for (int nt = 0; nt < 4; nt++)
                MMA16816(c[mt][nt], ah[mt], bh[nt>>1][(nt&1)*2], bh[nt>>1][(nt&1)*2+1]);
#pragma unroll
        for (int mt = 0; mt < 4; mt++)
#pragma unroll
            for (int nt = 0; nt < 4; nt++)
                MMA16816(c[mt][nt], ah[mt], bl[nt>>1][(nt&1)*2], bl[nt>>1][(nt&1)*2+1]);
    }
}

__device__ __forceinline__ void copy_chunk2(u32 base, int tid, int ch,
        const u32* pah, const u32* pal, const u32* pbh, const u32* pbl){
#pragma unroll
    for (int it = 0; it < 4; it++){
        int i = it*512 + tid;
        int row = i >> 3, pg = (i & 7)*4;
        size_t ga = (size_t)row*128 + ch*32 + pg;
        u32 off = base + (u32)(row*PITCHB + pg*4);
        CPA16(off + S2A_H, pah + ga);
        CPA16(off + S2A_L, pal + ga);
    }
#pragma unroll
    for (int it = 0; it < 2; it++){
        int i = it*512 + tid;
        int row = i >> 3, pg = (i & 7)*4;
        size_t gb = (size_t)row*128 + ch*32 + pg;
        u32 off = base + (u32)(row*PITCHB + pg*4);
        CPA16(off + S2B_H, pbh + gb);
        CPA16(off + S2B_L, pbl + gb);
    }
}

__device__ __forceinline__ void copy_chunk2f(u32 base, int tid, int ch,
        const u32* pah, const u32* pbh, const u32* pbl){
#pragma unroll
    for (int it = 0; it < 4; it++){
        int i = it*512 + tid;
        int row = i >> 3, pg = (i & 7)*4;
        size_t ga = (size_t)row*128 + ch*32 + pg;
        u32 off = base + (u32)(row*PITCHB + pg*4);
        CPA16(off + S2A_H, pah + ga);
    }
#pragma unroll
    for (int it = 0; it < 2; it++){
        int i = it*512 + tid;
        int row = i >> 3, pg = (i & 7)*4;
        size_t gb = (size_t)row*128 + ch*32 + pg;
        u32 off = base + (u32)(row*PITCHB + pg*4);
        CPA16(off + S2B_H, pbh + gb);
        CPA16(off + S2B_L, pbl + gb);
    }
}

__device__ __forceinline__ void gemm_pipe2(u32 smb, int tid, int wm, int wn, int lane,
        const u32* pah, const u32* pal, const u32* pbh, const u32* pbl,
        float c[4][4][4]){
    copy_chunk2(smb,        tid, 0, pah, pal, pbh, pbl);
    CP_COMMIT();
    copy_chunk2(smb + BUF2, tid, 1, pah, pal, pbh, pbl);
    CP_COMMIT();
#pragma unroll
    for (int ch = 0; ch < 4; ch++){
        if (ch < 3) CP_WAIT1(); else CP_WAIT0();
        __syncthreads();
        mma_chunk2(smb + (ch & 1)*BUF2, wm, wn, lane, c);
        __syncthreads();
        if (ch < 2){
            copy_chunk2(smb + (ch & 1)*BUF2, tid, ch + 2, pah, pal, pbh, pbl);
            CP_COMMIT();
        }
    }
}

__device__ __forceinline__ void gemm_pipe2f(u32 smb, int tid, int wm, int wn, int lane,
        const u32* pah, const u32* pbh, const u32* pbl,
        float c[4][4][4]){
    copy_chunk2f(smb,        tid, 0, pah, pbh, pbl);
    CP_COMMIT();
    copy_chunk2f(smb + BUF2, tid, 1, pah, pbh, pbl);
    CP_COMMIT();
#pragma unroll
    for (int ch = 0; ch < 4; ch++){
        if (ch < 3) CP_WAIT1(); else CP_WAIT0();
        __syncthreads();
        mma_chunk2f(smb + (ch & 1)*BUF2, wm, wn, lane, c);
        __syncthreads();
        if (ch < 2){
            copy_chunk2f(smb + (ch & 1)*BUF2, tid, ch + 2, pah, pbh, pbl);
            CP_COMMIT();
        }
    }
}

/* ------------------------------------------------------------------ */
/* K1: QKV GEMM — 256x128 tile, 512 thr, double-buffered, 3-pass.      */
/* ------------------------------------------------------------------ */
__global__ void __launch_bounds__(512, 1) k_qkv_t(){
    extern __shared__ char sm[];
    u32 smb = smem_u32(sm);
    int tid = threadIdx.x, wid = tid >> 5, lane = tid & 31;
    int oc = blockIdx.x;
    int t0 = blockIdx.y * 256;
    int wsel = oc >> 1;
    u32* dsth = (oc < 2) ? g_qh : (oc < 4 ? g_kh : g_vh);
    u32* dstl = (oc < 2) ? g_ql : (oc < 4 ? g_kl : g_vl);
    int or0 = (oc & 1) * 128;

    const u32* pah = g_xh + (size_t)t0*128;
    const u32* pal = g_xl + (size_t)t0*128;
    const u32* pbh = g_wh + (size_t)wsel*32768 + (size_t)or0*128;
    const u32* pbl = g_wl + (size_t)wsel*32768 + (size_t)or0*128;

    int wm = (wid >> 2) * 64, wn = (wid & 3) * 32;

    float c[4][4][4];
#pragma unroll
    for (int mt = 0; mt < 4; mt++)
#pragma unroll
        for (int nt = 0; nt < 4; nt++)
#pragma unroll
            for (int r = 0; r < 4; r++) c[mt][nt][r] = 0.f;

    gemm_pipe2(smb, tid, wm, wn, lane, pah, pal, pbh, pbl, c);

    u32* SH = (u32*)sm;
    u32* SL = (u32*)(sm + 69632);
#pragma unroll
    for (int mt = 0; mt < 4; mt++){
#pragma unroll
        for (int nt = 0; nt < 4; nt++){
            int r = wm + mt*16 + (lane >> 2);
            int cp = (wn + nt*8 + (lane & 3)*2) >> 1;
            u32 h, l;
            f16split2(c[mt][nt][0], c[mt][nt][1], h, l);
            SH[r*68 + cp] = h; SL[r*68 + cp] = l;
            f16split2(c[mt][nt][2], c[mt][nt][3], h, l);
            SH[(r+8)*68 + cp] = h; SL[(r+8)*68 + cp] = l;
        }
    }
    __syncthreads();
#pragma unroll
    for (int it = 0; it < 8; it++){
        int i = it*512 + tid;
        int row = i >> 4, c4 = (i & 15)*4;
        size_t g = (size_t)(t0 + row)*128 + (or0 >> 1) + c4;
        *(uint4*)&dsth[g] = *(uint4*)&SH[row*68 + c4];
        *(uint4*)&dstl[g] = *(uint4*)&SL[row*68 + c4];
    }
}

/* ------------------------------------------------------------------ */
/* K5: final GEMM — 256x128 tile, 512 thr, 2-pass (A hi only).         */
/* ------------------------------------------------------------------ */
__global__ void __launch_bounds__(512, 1) k_final_t(float* __restrict__ out){
    extern __shared__ char sm[];
    u32 smb = smem_u32(sm);
    int tid = threadIdx.x, wid = tid >> 5, lane = tid & 31;
    int o0 = blockIdx.x * 128;
    int t0 = blockIdx.y * 256;
    int b = t0 / NN, tl0 = t0 % NN;

    const u32* pah = g_ah + (size_t)t0*128;
    const u32* pbh = g_wch + (size_t)o0*128;
    const u32* pbl = g_wcl + (size_t)o0*128;

    int wm = (wid >> 2) * 64, wn = (wid & 3) * 32;

    float c[4][4][4];
#pragma unroll
    for (int mt = 0; mt < 4; mt++)
#pragma unroll
        for (int nt = 0; nt < 4; nt++)
#pragma unroll
            for (int r = 0; r < 4; r++) c[mt][nt][r] = 0.f;

    gemm_pipe2f(smb, tid, wm, wn, lane, pah, pbh, pbl, c);

    float* stage = (float*)sm;
#pragma unroll
    for (int mt = 0; mt < 4; mt++){
#pragma unroll
        for (int nt = 0; nt < 4; nt++){
            int r = wm + mt*16 + (lane >> 2);
            int cc = wn + nt*8 + (lane & 3)*2;
            stage[cc*260 + r]         = c[mt][nt][0];
            stage[(cc+1)*260 + r]     = c[mt][nt][1];
            stage[cc*260 + r + 8]     = c[mt][nt][2];
            stage[(cc+1)*260 + r + 8] = c[mt][nt][3];
        }
    }
    __syncthreads();
#pragma unroll
    for (int i2 = 0; i2 < 16; i2++){
        int idx = i2*512 + tid;
        int cc = idx >> 6, t4 = (idx & 63) * 4;
        int o = o0 + cc;
        float bias = g_bc[o];
        float4 v = *(float4*)&stage[cc*260 + t4];
        v.x += bias; v.y += bias; v.z += bias; v.w += bias;
        *(float4*)&out[((size_t)b*256 + o)*NN + tl0 + t4] = v;
    }
}

/* ------------------------------------------------------------------ */
/* K2: key-dash max — 2-pass (k residual dropped), 2 tiles per block.  */
/* grid (36, 32).                                                      */
/* ------------------------------------------------------------------ */
__global__ void __launch_bounds__(256) k_kmax(){
    __shared__ u32 projh[128*20];
    __shared__ u32 projl[128*20];
    __shared__ u32 kth[128*20];
    __shared__ float red[256];
    int bh = blockIdx.y, b = bh >> 3, h = bh & 7;
    int t = threadIdx.x, wid = t >> 5, lane = t & 31;

#pragma unroll
    for (int r = 0; r < 2; r++){
        int i = r*256 + t;
        int m = i >> 2, q4 = (i & 3)*4;
        *(uint4*)&projh[m*20 + q4] = *(const uint4*)&g_projh[m*16 + q4];
        *(uint4*)&projl[m*20 + q4] = *(const uint4*)&g_projl[m*16 + q4];
    }

    int wm = (wid >> 1)*32, wn = (wid & 1)*64;
    u32 smPH = smem_u32(projh), smPL = smem_u32(projl);
    u32 smKH = smem_u32(kth);
    u32 a_off = (u32)((wm + (lane & 15))*80 + (lane >> 4)*16);
    u32 b_off = (u32)((wn + (lane & 7) + ((lane >> 4) & 1)*8)*80 + ((lane >> 3) & 1)*16);

    float mx = -1e30f;
    for (int tile = 0; tile < 2; tile++){
        int n0 = blockIdx.x * 256 + tile * 128;
#pragma unroll
        for (int r = 0; r < 2; r++){
            int i = r*256 + t;
            int m = i >> 2, q4 = (i & 3)*4;
            size_t g = (size_t)(b*NN + n0 + m)*128 + h*16 + q4;
            *(uint4*)&kth[m*20 + q4] = *(const uint4*)&g_kh[g];
        }
        __syncthreads();

        float c[2][8][4];
#pragma unroll
        for (int mt = 0; mt < 2; mt++)
#pragma unroll
            for (int nt = 0; nt < 8; nt++)
#pragma unroll
                for (int r = 0; r < 4; r++) c[mt][nt][r] = 0.f;
#pragma unroll
        for (int ks = 0; ks < 2; ks++){
            u32 ah[2][4], al[2][4], bh2[4][4];
#pragma unroll
            for (int mt = 0; mt < 2; mt++)
                LDM4(ah[mt], smPH + a_off + mt*(16*80) + ks*32);
#pragma unroll
            for (int np = 0; np < 4; np++)
                LDM4(bh2[np], smKH + b_off + np*(16*80) + ks*32);
#pragma unroll
            for (int mt = 0; mt < 2; mt++)
                LDM4(al[mt], smPL + a_off + mt*(16*80) + ks*32);
#pragma unroll
            for (int mt = 0; mt < 2; mt++)
#pragma unroll
                for (int nt = 0; nt < 8; nt++)
                    MMA16816(c[mt][nt], ah[mt], bh2[nt>>1][(nt&1)*2], bh2[nt>>1][(nt&1)*2+1]);
#pragma unroll
            for (int mt = 0; mt < 2; mt++)
#pragma unroll
                for (int nt = 0; nt < 8; nt++)
                    MMA16816(c[mt][nt], al[mt], bh2[nt>>1][(nt&1)*2], bh2[nt>>1][(nt&1)*2+1]);
        }
#pragma unroll
        for (int mt = 0; mt < 2; mt++)
#pragma unroll
            for (int nt = 0; nt < 8; nt++)
#pragma unroll
                for (int r = 0; r < 4; r++) mx = fmaxf(mx, c[mt][nt][r]);
        __syncthreads();
    }
    red[t] = mx;
    __syncthreads();
    for (int s = 128; s > 0; s >>= 1){
        if (t < (unsigned)s) red[t] = fmaxf(red[t], red[t + s]);
        __syncthreads();
    }
    if (t == 0) atomicMaxF(&g_kmax[bh], red[0]);
}

/* ------------------------------------------------------------------ */
/* K3: fused key features + ctx. grid (9, 32) — one full wave.         */
/* mma1 2-pass (k residual dropped; KTL kept for exact diag).          */
/* ------------------------------------------------------------------ */
#define CP_PROJH 0
#define CP_PROJL 10240
#define CP_KTH   20480
#define CP_KTL   25600
#define CP_KPSH  30720
#define CP_KPSL  49152
#define CP_VTH   67584
#define CP_VTL   74752
#define CP_DIAG  81920
#define CTX_SMEM 82176
#define CTX_SPLITS 9
#define CTX_TILES  16

__global__ void __launch_bounds__(256) k_ctx2(){
    extern __shared__ char sm[];
    u32 smb = smem_u32(sm);
    int bh = blockIdx.y, b = bh >> 3, h = bh & 7;
    int sp = blockIdx.x;
    int t = threadIdx.x, wid = t >> 5, lane = t & 31;
    float gmax = g_kmax[bh];

    u32* PJH = (u32*)(sm + CP_PROJH); u32* PJL = (u32*)(sm + CP_PROJL);
    u32* KTH = (u32*)(sm + CP_KTH);   u32* KTL = (u32*)(sm + CP_KTL);
    u32* VTH = (u32*)(sm + CP_VTH);   u32* VTL = (u32*)(sm + CP_VTL);
    float* DIAG = (float*)(sm + CP_DIAG);

#pragma unroll
    for (int r = 0; r < 2; r++){
        int i = r*256 + t;
        int m = i >> 2, q4 = (i & 3)*4;
        *(uint4*)&PJH[m*20 + q4] = *(const uint4*)&g_projh[m*16 + q4];
        *(uint4*)&PJL[m*20 + q4] = *(const uint4*)&g_projl[m*16 + q4];
    }
    for (int i = t; i < 1536; i += 256){
        int mat = (i >= 768), rem = (i >= 768) ? i - 768 : i;
        int tok = rem / 12, cc = 16 + rem % 12;
        u32 v = (mat == 0 && cc == 16) ? 0x00003C00u : 0u;
        ((mat == 0) ? VTH : VTL)[tok*28 + cc] = v;
    }

    int wm1 = (wid >> 1)*32, wn1 = (wid & 1)*32;
    u32 a1_off = (u32)((wm1 + (lane & 15))*80 + (lane >> 4)*16);
    u32 b1_off = (u32)((wn1 + (lane & 7) + ((lane >> 4) & 1)*8)*80 + ((lane >> 3) & 1)*16);
    int wm2 = (wid >> 1)*32, wn2 = (wid & 1)*24;
    u32 a2_off = (u32)((wm2 + (lane & 15))*144 + (lane >> 4)*16);
    u32 b2row = (u32)(((lane & 7) + ((lane >> 3) & 1)*8)*112);
    u32 b2col0 = (u32)((wn2 + ((lane >> 4) & 1)*8)*2);

    float c2[2][3][4];
#pragma unroll
    for (int mt = 0; mt < 2; mt++)
#pragma unroll
        for (int nt = 0; nt < 3; nt++)
#pragma unroll
            for (int r = 0; r < 4; r++) c2[mt][nt][r] = 0.f;

    for (int it = 0; it < CTX_TILES; it++){
        int n0 = sp*(CTX_TILES*64) + it*64;
        {
            int tok = t >> 2, q4 = (t & 3)*4;
            size_t g = (size_t)(b*NN + n0 + tok)*128 + h*16 + q4;
            *(uint4*)&KTH[tok*20 + q4] = *(const uint4*)&g_kh[g];
            *(uint4*)&KTL[tok*20 + q4] = *(const uint4*)&g_kl[g];
            *(uint4*)&VTH[tok*28 + q4] = *(const uint4*)&g_vh[g];
            *(uint4*)&VTL[tok*28 + q4] = *(const uint4*)&g_vl[g];
        }
        __syncthreads();
        if (t < 64){
            float sq = 0.f;
#pragma unroll
            for (int i = 0; i < 16; i++){
                float2 v = h2f(KTH[t*20 + i], KTL[t*20 + i]);
                sq += v.x*v.x + v.y*v.y;
            }
            DIAG[t] = HALF_NRM2 * sq;
        }
        __syncthreads();

        /* mma1: dash = projn . k  (2-pass: ph·kh + pl·kh) */
        float c1[2][4][4];
#pragma unroll
        for (int mt = 0; mt < 2; mt++)
#pragma unroll
            for (int nt = 0; nt < 4; nt++)
#pragma unroll
                for (int r = 0; r < 4; r++) c1[mt][nt][r] = 0.f;
#pragma unroll
        for (int ks = 0; ks < 2; ks++){
            u32 ah[2][4], al[2][4], bhh[2][4];
#pragma unroll
            for (int mt = 0; mt < 2; mt++)
                LDM4(ah[mt], smb + CP_PROJH + a1_off + mt*(16*80) + ks*32);
#pragma unroll
            for (int np = 0; np < 2; np++)
                LDM4(bhh[np], smb + CP_KTH + b1_off + np*(16*80) + ks*32);
#pragma unroll
            for (int mt = 0; mt < 2; mt++)
                LDM4(al[mt], smb + CP_PROJL + a1_off + mt*(16*80) + ks*32);
#pragma unroll
            for (int mt = 0; mt < 2; mt++)
#pragma unroll
                for (int nt = 0; nt < 4; nt++)
                    MMA16816(c1[mt][nt], ah[mt], bhh[nt>>1][(nt&1)*2], bhh[nt>>1][(nt&1)*2+1]);
#pragma unroll
            for (int mt = 0; mt < 2; mt++)
#pragma unroll
                for (int nt = 0; nt < 4; nt++)
                    MMA16816(c1[mt][nt], al[mt], bhh[nt>>1][(nt&1)*2], bhh[nt>>1][(nt&1)*2+1]);
        }
        u32* KPH = (u32*)(sm + CP_KPSH);
        u32* KPL = (u32*)(sm + CP_KPSL);
#pragma unroll
        for (int mt = 0; mt < 2; mt++){
#pragma unroll
            for (int nt = 0; nt < 4; nt++){
                int col = wn1 + nt*8 + (lane & 3)*2;
                float d0 = DIAG[col] + gmax, d1 = DIAG[col+1] + gmax;
                int r0 = wm1 + mt*16 + (lane >> 2);
                float v0 = KP_RATIO*(__expf(c1[mt][nt][0] - d0) + EPSF);
                float v1 = KP_RATIO*(__expf(c1[mt][nt][1] - d1) + EPSF);
                float v2 = KP_RATIO*(__expf(c1[mt][nt][2] - d0) + EPSF);
                float v3 = KP_RATIO*(__expf(c1[mt][nt][3] - d1) + EPSF);
                u32 hh, ll;
                f16split2(v0, v1, hh, ll);
                KPH[r0*36 + (col>>1)] = hh; KPL[r0*36 + (col>>1)] = ll;
                f16split2(v2, v3, hh, ll);
                KPH[(r0+8)*36 + (col>>1)] = hh; KPL[(r0+8)*36 + (col>>1)] = ll;
            }
        }
        __syncthreads();

#pragma unroll
        for (int ks = 0; ks < 4; ks++){
            u32 ah[2][4], al[2][4], bhh[2][4];
            u32 rb = (u32)(ks*16*112) + b2row;
#pragma unroll
            for (int mt = 0; mt < 2; mt++)
                LDM4(ah[mt], smb + CP_KPSH + a2_off + mt*(16*144) + ks*32);
#pragma unroll
            for (int np = 0; np < 2; np++)
                LDM4T(bhh[np], smb + CP_VTH + rb + b2col0 + np*32);
#pragma unroll
            for (int mt = 0; mt < 2; mt++)
                LDM4(al[mt], smb + CP_KPSL + a2_off + mt*(16*144) + ks*32);
#pragma unroll
            for (int mt = 0; mt < 2; mt++)
#pragma unroll
                for (int nt = 0; nt < 3; nt++)
                    MMA16816(c2[mt][nt], ah[mt], bhh[nt>>1][(nt&1)*2], bhh[nt>>1][(nt&1)*2+1]);
#pragma unroll
            for (int mt = 0; mt < 2; mt++)
#pragma unroll
                for (int nt = 0; nt < 3; nt++)
                    MMA16816(c2[mt][nt], al[mt], bhh[nt>>1][(nt&1)*2], bhh[nt>>1][(nt&1)*2+1]);
            {
                u32 bl[2][4];
#pragma unroll
                for (int np = 0; np < 2; np++)
                    LDM4T(bl[np], smb + CP_VTL + rb + b2col0 + np*32);
#pragma unroll
                for (int mt = 0; mt < 2; mt++)
#pragma unroll
                    for (int nt = 0; nt < 3; nt++)
                        MMA16816(c2[mt][nt], ah[mt], bl[nt>>1][(nt&1)*2], bl[nt>>1][(nt&1)*2+1]);
            }
        }
        __syncthreads();
    }

#pragma unroll
    for (int mt = 0; mt < 2; mt++){
#pragma unroll
        for (int nt = 0; nt < 3; nt++){
            int m = wm2 + mt*16 + (lane >> 2);
            int n = wn2 + nt*8 + (lane & 3)*2;
            size_t base = ((size_t)bh*MF + m)*33;
            if (n < 33)   atomicAdd(&g_ctx[base + n],     c2[mt][nt][0]);
            if (n+1 < 33) atomicAdd(&g_ctx[base + n + 1], c2[mt][nt][1]);
            if (n < 33)   atomicAdd(&g_ctx[base + 264 + n],     c2[mt][nt][2]);
            if (n+1 < 33) atomicAdd(&g_ctx[base + 264 + n + 1], c2[mt][nt][3]);
        }
    }
}

/* ------------------------------------------------------------------ */
/* K4: fused query features + qp@ctx + d_inv. 2 tiles/block.           */
/* mma1 2-pass (q residual dropped; QTL kept for exact diag).          */
/* grid (72, 32), 256 thr.                                             */
/* ------------------------------------------------------------------ */
#define QP_PROJH 0
#define QP_PROJL 10240
#define QP_QTH   20480
#define QP_QTL   25600
#define QP_QPSH  30720
#define QP_QPSL  49152
#define QP_CTH   67584
#define QP_CTL   84992
#define QP_PM    102400
#define QP_RMAX  103424
#define QP_DIAG  103680
#define QP_STG   QP_QPSH
#define QA_SMEM  103936

__global__ void __launch_bounds__(256) k_qattn2(){
    extern __shared__ char sm[];
    u32 smb = smem_u32(sm);
    int bh = blockIdx.y, b = bh >> 3, h = bh & 7;
    int t = threadIdx.x, wid = t >> 5, lane = t & 31;

    u32* PJH = (u32*)(sm + QP_PROJH); u32* PJL = (u32*)(sm + QP_PROJL);
    u32* QTH = (u32*)(sm + QP_QTH);   u32* QTL = (u32*)(sm + QP_QTL);
    u32* CTH = (u32*)(sm + QP_CTH);   u32* CTL = (u32*)(sm + QP_CTL);
    float* PM = (float*)(sm + QP_PM);
    float* RMAX = (float*)(sm + QP_RMAX);
    float* DIAG = (float*)(sm + QP_DIAG);

#pragma unroll
    for (int r = 0; r < 2; r++){
        int i = r*256 + t;
        int m = i >> 2, q4 = (i & 3)*4;
        *(uint4*)&PJH[m*20 + q4] = *(const uint4*)&g_projh[m*16 + q4];
        *(uint4*)&PJL[m*20 + q4] = *(const uint4*)&g_projl[m*16 + q4];
    }
#pragma unroll
    for (int r = 0; r < 4; r++){
        int i = r*256 + t;
        int j = i >> 4, q4 = (i & 15)*4;
        *(uint4*)&CTH[j*68 + q4] = *(const uint4*)&g_ctxh2[bh*4096 + j*64 + q4];
        *(uint4*)&CTL[j*68 + q4] = *(const uint4*)&g_ctxl2[bh*4096 + j*64 + q4];
    }

    int wm1 = (wid >> 1)*32, wn1 = (wid & 1)*32;
    u32 a1_off = (u32)((wm1 + (lane & 15))*80 + (lane >> 4)*16);
    u32 b1_off = (u32)((wn1 + (lane & 7) + ((lane >> 4) & 1)*8)*80 + ((lane >> 3) & 1)*16);
    int wm2 = (wid >> 1)*16, wn2 = (wid & 1)*32;
    u32 a2_off = (u32)((wm2 + (lane & 15))*272 + (lane >> 4)*16);

    for (int tile = 0; tile < 2; tile++){
        int n0 = blockIdx.x * 128 + tile * 64;
        {
            int tok = t >> 2, q4 = (t & 3)*4;
            size_t g = (size_t)(b*NN + n0 + tok)*128 + h*16 + q4;
            *(uint4*)&QTH[tok*20 + q4] = *(const uint4*)&g_qh[g];
            *(uint4*)&QTL[tok*20 + q4] = *(const uint4*)&g_ql[g];
        }
        __syncthreads();
        if (t < 64){
            float sq = 0.f;
#pragma unroll
            for (int i = 0; i < 16; i++){
                float2 v = h2f(QTH[t*20 + i], QTL[t*20 + i]);
                sq += v.x*v.x + v.y*v.y;
            }
            DIAG[t] = HALF_NRM2 * sq;
        }
        __syncthreads();

        /* mma1: dash = projn . q (2-pass) */
        float c1[2][4][4];
#pragma unroll
        for (int mt = 0; mt < 2; mt++)
#pragma unroll
            for (int nt = 0; nt < 4; nt++)
#pragma unroll
                for (int r = 0; r < 4; r++) c1[mt][nt][r] = 0.f;
#pragma unroll
        for (int ks = 0; ks < 2; ks++){
            u32 ah[2][4], al[2][4], bhh[2][4];
#pragma unroll
            for (int mt = 0; mt < 2; mt++)
                LDM4(ah[mt], smb + QP_PROJH + a1_off + mt*(16*80) + ks*32);
#pragma unroll
            for (int np = 0; np < 2; np++)
                LDM4(bhh[np], smb + QP_QTH + b1_off + np*(16*80) + ks*32);
#pragma unroll
            for (int mt = 0; mt < 2; mt++)
                LDM4(al[mt], smb + QP_PROJL + a1_off + mt*(16*80) + ks*32);
#pragma unroll
            for (int mt = 0; mt < 2; mt++)
#pragma unroll
                for (int nt = 0; nt < 4; nt++)
                    MMA16816(c1[mt][nt], ah[mt], bhh[nt>>1][(nt&1)*2], bhh[nt>>1][(nt&1)*2+1]);
#pragma unroll
            for (int mt = 0; mt < 2; mt++)
#pragma unroll
                for (int nt = 0; nt < 4; nt++)
                    MMA16816(c1[mt][nt], al[mt], bhh[nt>>1][(nt&1)*2], bhh[nt>>1][(nt&1)*2+1]);
        }

#pragma unroll
        for (int nt = 0; nt < 4; nt++){
            float me = fmaxf(fmaxf(c1[0][nt][0], c1[0][nt][2]),
                             fmaxf(c1[1][nt][0], c1[1][nt][2]));
            float mo = fmaxf(fmaxf(c1[0][nt][1], c1[0][nt][3]),
                             fmaxf(c1[1][nt][1], c1[1][nt][3]));
#pragma unroll
            for (int s = 4; s < 32; s <<= 1){
                me = fmaxf(me, __shfl_xor_sync(0xFFFFFFFF, me, s));
                mo = fmaxf(mo, __shfl_xor_sync(0xFFFFFFFF, mo, s));
            }
            if ((lane >> 2) == 0){
                int col = wn1 + nt*8 + (lane & 3)*2;
                PM[(wid >> 1)*64 + col]     = me;
                PM[(wid >> 1)*64 + col + 1] = mo;
            }
        }
        __syncthreads();
        if (t < 64){
            float mx = PM[t];
            mx = fmaxf(mx, PM[64 + t]);
            mx = fmaxf(mx, PM[128 + t]);
            mx = fmaxf(mx, PM[192 + t]);
            RMAX[t] = mx;
        }
        __syncthreads();

        {
            u32* QPH = (u32*)(sm + QP_QPSH);
            u32* QPL = (u32*)(sm + QP_QPSL);
#pragma unroll
            for (int mt = 0; mt < 2; mt++){
#pragma unroll
                for (int nt = 0; nt < 4; nt++){
                    int col = wn1 + nt*8 + (lane & 3)*2;
                    float d0 = DIAG[col] + RMAX[col], d1 = DIAG[col+1] + RMAX[col+1];
                    int r0 = wm1 + mt*16 + (lane >> 2);
                    float v0 = QP_RATIO*(__expf(c1[mt][nt][0] - d0) + EPSF);
                    float v1 = QP_RATIO*(__expf(c1[mt][nt][1] - d1) + EPSF);
                    float v2 = QP_RATIO*(__expf(c1[mt][nt][2] - d0) + EPSF);
                    float v3 = QP_RATIO*(__expf(c1[mt][nt][3] - d1) + EPSF);
                    u32 hh, ll;
                    f16split2(v0, v1, hh, ll);
                    QPH[r0*36 + (col>>1)] = hh; QPL[r0*36 + (col>>1)] = ll;
                    f16split2(v2, v3, hh, ll);
                    QPH[(r0+8)*36 + (col>>1)] = hh; QPL[(r0+8)*36 + (col>>1)] = ll;
                }
            }
        }
        __syncthreads();

        float c2[4][4];
#pragma unroll
        for (int nt = 0; nt < 4; nt++)
#pragma unroll
            for (int r = 0; r < 4; r++) c2[nt][r] = 0.f;
#pragma unroll
        for (int ks = 0; ks < 8; ks++){
            u32 ah[4], al[4], bt[2][4], btl[2][4];
            LDM4(ah, smb + QP_CTH + a2_off + ks*32);
            LDM4(al, smb + QP_CTL + a2_off + ks*32);
            u32 rowb = (u32)((ks*16 + (lane & 7) + ((lane >> 3) & 1)*8)*144);
#pragma unroll
            for (int np = 0; np < 2; np++){
                u32 colb = (u32)((wn2 + np*16 + ((lane >> 4) & 1)*8)*2);
                LDM4T(bt[np],  smb + QP_QPSH + rowb + colb);
                LDM4T(btl[np], smb + QP_QPSL + rowb + colb);
            }
#pragma unroll
            for (int nt = 0; nt < 4; nt++){
                MMA16816(c2[nt], ah, bt[nt>>1][(nt&1)*2],  bt[nt>>1][(nt&1)*2+1]);
                MMA16816(c2[nt], ah, btl[nt>>1][(nt&1)*2], btl[nt>>1][(nt&1)*2+1]);
                MMA16816(c2[nt], al, bt[nt>>1][(nt&1)*2],  bt[nt>>1][(nt&1)*2+1]);
            }
        }
        __syncthreads();

        float* STG = (float*)(sm + QP_STG);
#pragma unroll
        for (int nt = 0; nt < 4; nt++){
            int j = wm2 + (lane >> 2);
            int tok = wn2 + nt*8 + (lane & 3)*2;
            if (j <= 32){
                STG[j*68 + tok]     = c2[nt][0];
                STG[j*68 + tok + 1] = c2[nt][1];
            }
            if (j + 8 <= 32){
                STG[(j+8)*68 + tok]     = c2[nt][2];
                STG[(j+8)*68 + tok + 1] = c2[nt][3];
            }
        }
        __syncthreads();

        {
            int tok = t >> 2, jb = (t & 3)*8;
            float inv = 1.0f / STG[32*68 + tok];
            u32 hv[4], lv[4];
#pragma unroll
            for (int p = 0; p < 4; p++){
                float v0 = STG[(jb + 2*p)*68 + tok] * inv;
                float v1 = STG[(jb + 2*p + 1)*68 + tok] * inv;
                f16split2(v0, v1, hv[p], lv[p]);
            }
            size_t base = (size_t)(b*NN + n0 + tok)*128 + h*16 + (jb >> 1);
            *(uint4*)&g_ah[base] = make_uint4(hv[0], hv[1], hv[2], hv[3]);
            *(uint4*)&g_al[base] = make_uint4(lv[0], lv[1], lv[2], lv[3]);
        }
        __syncthreads();
    }
}

/* ------------------------------------------------------------------ */
extern "C" void kernel_launch(void* const* d_in, const int* in_sizes, int n_in,
                              void* d_out, int out_size){
    const float* x    = (const float*)d_in[0];
    const float* wq   = (const float*)d_in[1];
    const float* wk   = (const float*)d_in[2];
    const float* wv   = (const float*)d_in[3];
    const float* wo   = (const float*)d_in[4];
    const float* bo   = (const float*)d_in[5];
    const float* proj = (const float*)d_in[6];
    const float* wp   = (const float*)d_in[7];
    const float* bp   = (const float*)d_in[8];
    float* out = (float*)d_out;

    cudaFuncSetAttribute(k_qkv_t,   cudaFuncAttributeMaxDynamicSharedMemorySize, G4_SMEM);
    cudaFuncSetAttribute(k_final_t, cudaFuncAttributeMaxDynamicSharedMemorySize, G4_SMEM);
    cudaFuncSetAttribute(k_ctx2,    cudaFuncAttributeMaxDynamicSharedMemorySize, CTX_SMEM);
    cudaFuncSetAttribute(k_qattn2,  cudaFuncAttributeMaxDynamicSharedMemorySize, QA_SMEM);

    k_misc<<<1176, 256>>>(wq, wk, wv, proj, wo, bo, wp, bp);
    k_xcvt<<<TT/128, 256>>>(x);
    k_qkv_t<<<dim3(6, TT/256), 512, G4_SMEM>>>();
    k_kmax<<<dim3(NN/256, 32), 256>>>();
    k_ctx2<<<dim3(CTX_SPLITS, 32), 256, CTX_SMEM>>>();
    k_ctx_cvt<<<32, 256>>>();
    k_qattn2<<<dim3(NN/128, 32), 256, QA_SMEM>>>();
    k_final_t<<<dim3(2, TT/256), 512, G4_SMEM>>>(out);
}

// round 17
// speedup vs baseline: 1.1834x; 1.0671x over previous
#include <cuda_runtime.h>
#include <cuda_fp16.h>
#include <math.h>

#define BB 4
#define CC 256
#define NHEAD 8
#define DHEAD 32
#define MF 128
#define NN 9216
#define TT (BB*NN)   /* 36864 */

#define NRM       0.4204482076268573f     /* 32^-0.25 */
#define HALF_NRM2 0.08838834764831845f    /* 0.5 * 32^-0.5 */
#define RATIO     0.08838834764831845f    /* 128^-0.5 */
#define EPSF      1e-4f
#define KP_SCALE  64.0f
#define QP_SCALE  64.0f
#define KP_RATIO  (RATIO*KP_SCALE)
#define QP_RATIO  (RATIO*QP_SCALE)

typedef unsigned long long u64;
typedef unsigned int u32;

/* ---------------- mma.sync helpers ---------------- */
__device__ __forceinline__ u32 smem_u32(const void* p){
    u32 a; asm("{ .reg .u64 t; cvta.to.shared.u64 t, %1; cvt.u32.u64 %0, t; }"
               : "=r"(a) : "l"(p)); return a;
}
#define LDM4(r, a) \
    asm volatile("ldmatrix.sync.aligned.m8n8.x4.shared.b16 {%0,%1,%2,%3}, [%4];" \
        : "=r"((r)[0]),"=r"((r)[1]),"=r"((r)[2]),"=r"((r)[3]) : "r"(a))
#define LDM4T(r, a) \
    asm volatile("ldmatrix.sync.aligned.m8n8.x4.trans.shared.b16 {%0,%1,%2,%3}, [%4];" \
        : "=r"((r)[0]),"=r"((r)[1]),"=r"((r)[2]),"=r"((r)[3]) : "r"(a))
#define MMA16816(c, a, b0, b1) \
    asm volatile("mma.sync.aligned.m16n8k16.row.col.f32.f16.f16.f32 " \
        "{%0,%1,%2,%3}, {%4,%5,%6,%7}, {%8,%9}, {%0,%1,%2,%3};" \
        : "+f"((c)[0]),"+f"((c)[1]),"+f"((c)[2]),"+f"((c)[3]) \
        : "r"((a)[0]),"r"((a)[1]),"r"((a)[2]),"r"((a)[3]), "r"(b0),"r"(b1))
#define CPA16(dst, src) \
    asm volatile("cp.async.cg.shared.global [%0], [%1], 16;" :: "r"(dst), "l"(src))
#define CP_COMMIT() asm volatile("cp.async.commit_group;")
#define CP_WAIT0()  asm volatile("cp.async.wait_group 0;")
#define CP_WAIT1()  asm volatile("cp.async.wait_group 1;")

__device__ __forceinline__ void f16split2(float a, float b, u32 &h, u32 &l){
    __half2 hh = __floats2half2_rn(a, b);
    float2 bk = __half22float2(hh);
    __half2 ll = __floats2half2_rn(a - bk.x, b - bk.y);
    h = *(u32*)&hh; l = *(u32*)&ll;
}
__device__ __forceinline__ u32 f16pack2(float a, float b){
    __half2 hh = __floats2half2_rn(a, b);
    return *(u32*)&hh;
}
__device__ __forceinline__ float2 h2f(u32 h, u32 l){
    float2 a = __half22float2(*(__half2*)&h);
    float2 b = __half22float2(*(__half2*)&l);
    return make_float2(a.x + b.x, a.y + b.y);
}

/* big-tile GEMM smem: per buffer A 256x32h x2 + B 128x32h x2, pitch 144 */
#define PITCHB 144
#define S2A_H 0
#define S2A_L 36864
#define S2B_H 73728
#define S2B_L 92160
#define BUF2  110592
#define G4_SMEM 221184

/* ---------------- scratch ---------------- */
__device__ u32 g_xh[(size_t)TT*128];
__device__ u32 g_xl[(size_t)TT*128];
__device__ u32 g_qh[(size_t)TT*128];
__device__ u32 g_ql[(size_t)TT*128];
__device__ u32 g_kh[(size_t)TT*128];
__device__ u32 g_kl[(size_t)TT*128];
__device__ u32 g_vh[(size_t)TT*128];
__device__ u32 g_vl[(size_t)TT*128];
__device__ u32 g_ah[(size_t)TT*128];
__device__ u32 g_al[(size_t)TT*128];
__device__ u32 g_wh[3*256*128];
__device__ u32 g_wl[3*256*128];
__device__ u32 g_wch[256*128];
__device__ u32 g_wcl[256*128];
__device__ float g_kmax[32];
__device__ float g_ctx[32*MF*33];
__device__ u32 g_ctxh2[32*64*64];
__device__ u32 g_ctxl2[32*64*64];
__device__ float g_bc[CC];
__device__ u32 g_projh[2048];
__device__ u32 g_projl[2048];

__device__ __forceinline__ void atomicMaxF(float* a, float v){
    int old = __float_as_int(*a);
    while (__int_as_float(old) < v){
        int cur = atomicCAS((int*)a, old, __float_as_int(v));
        if (cur == old) break;
        old = cur;
    }
}

/* ------------------------------------------------------------------ */
/* K_misc: Wc fold+split, w split, proj split, inits — one launch.     */
/* ------------------------------------------------------------------ */
__global__ void k_misc(const float* __restrict__ wq, const float* __restrict__ wk,
                       const float* __restrict__ wv, const float* __restrict__ proj,
                       const float* __restrict__ wo, const float* __restrict__ bo,
                       const float* __restrict__ wp, const float* __restrict__ bp){
    __shared__ float row[256];
    int bid = blockIdx.x, t = threadIdx.x;
    if (bid < 256){
        int o2 = bid;
        float s = 0.f;
        for (int o = 0; o < 256; o++) s += wp[o2*256 + o] * wo[o*256 + t];
        row[t] = s;
        if (t == 0){
            float sb = 0.f;
            for (int o = 0; o < 256; o++) sb += wp[o2*256 + o] * bo[o];
            g_bc[o2] = sb + bp[o2];
        }
        __syncthreads();
        if (t < 128){
            u32 h, l;
            f16split2(row[2*t], row[2*t + 1], h, l);
            g_wch[o2*128 + t] = h;
            g_wcl[o2*128 + t] = l;
        }
    } else if (bid < 640){
        int i = (bid - 256)*256 + t;
        int oc = i >> 15, rem = i & 32767;
        int r = rem >> 7, p = rem & 127;
        const float* W = (oc == 0) ? wq : (oc == 1 ? wk : wv);
        u32 h, l;
        f16split2(W[r*256 + p*2], W[r*256 + p*2 + 1], h, l);
        g_wh[i] = h; g_wl[i] = l;
    } else if (bid < 648){
        int i = (bid - 640)*256 + t;
        int m = i >> 4, p = i & 15;
        u32 h, l;
        f16split2(proj[m*32 + p*2]*NRM, proj[m*32 + p*2 + 1]*NRM, h, l);
        g_projh[i] = h; g_projl[i] = l;
        if (bid == 640 && t < 32) g_kmax[t] = -1e30f;
    } else {
        int i = (bid - 648)*256 + t;
        if (i < 32*MF*33) g_ctx[i] = 0.f;
    }
}

__global__ void k_ctx_cvt(){
    int bh = blockIdx.x, t = threadIdx.x;
    for (int i = t; i < 4096; i += 256){
        int j = i >> 6, mp = i & 63;
        float a = 0.f, b = 0.f;
        if (j < 33){
            a = g_ctx[((size_t)bh*MF + mp*2)*33 + j];
            b = g_ctx[((size_t)bh*MF + mp*2 + 1)*33 + j];
        }
        u32 h, l;
        f16split2(a, b, h, l);
        g_ctxh2[bh*4096 + i] = h;
        g_ctxl2[bh*4096 + i] = l;
    }
}

/* ------------------------------------------------------------------ */
/* K_xcvt: transpose+split x -> g_xh/g_xl [token][128 pairs]           */
/* ------------------------------------------------------------------ */
__global__ void __launch_bounds__(256) k_xcvt(const float* __restrict__ x){
    __shared__ u32 sh[128*33];
    __shared__ u32 sl[128*33];
    int tid = threadIdx.x, wid = tid >> 5, lane = tid & 31;
    int t0 = blockIdx.x * 128;
    int b = t0 / NN, tl0 = t0 % NN;
    int tq = lane * 4, cg2 = wid * 2;

    for (int ch = 0; ch < 4; ch++){
        int c0 = ch * 64;
#pragma unroll
        for (int u = 0; u < 4; u++){
            int cl = u*16 + cg2;
            const float* p = &x[((size_t)(b*256 + c0 + cl))*NN + tl0 + tq];
            float4 f0 = *(const float4*)p;
            float4 f1 = *(const float4*)(p + NN);
            const float* e0 = (const float*)&f0;
            const float* e1 = (const float*)&f1;
#pragma unroll
            for (int j = 0; j < 4; j++){
                u32 h, l;
                f16split2(e0[j], e1[j], h, l);
                sh[(tq + j)*33 + (cl >> 1)] = h;
                sl[(tq + j)*33 + (cl >> 1)] = l;
            }
        }
        __syncthreads();
#pragma unroll
        for (int r = 0; r < 16; r++){
            int i = r*256 + tid;
            int row = i >> 5, p = i & 31;
            size_t g = (size_t)(t0 + row)*128 + ch*32 + p;
            g_xh[g] = sh[row*33 + p];
            g_xl[g] = sl[row*33 + p];
        }
        __syncthreads();
    }
}

/* ------------------------------------------------------------------ */
/* big-tile mma body: 3-pass (qkv)                                     */
/* ------------------------------------------------------------------ */
__device__ __forceinline__ void mma_chunk2(u32 base, int wm, int wn, int lane,
                                           float c[4][4][4]){
    u32 a_off = (u32)((wm + (lane & 15))*PITCHB + (lane >> 4)*16);
    u32 b_off = (u32)((wn + (lane & 7) + ((lane >> 4) & 1)*8)*PITCHB
                      + ((lane >> 3) & 1)*16);
#pragma unroll
    for (int ks = 0; ks < 4; ks++){
        u32 ah[4][4], al[4][4], bh[2][4];
#pragma unroll
        for (int mt = 0; mt < 4; mt++)
            LDM4(ah[mt], base + S2A_H + a_off + mt*(16*PITCHB) + ks*32);
#pragma unroll
        for (int np = 0; np < 2; np++)
            LDM4(bh[np], base + S2B_H + b_off + np*(16*PITCHB) + ks*32);
#pragma unroll
        for (int mt = 0; mt < 4; mt++)
            LDM4(al[mt], base + S2A_L + a_off + mt*(16*PITCHB) + ks*32);
#pragma unroll
        for (int mt = 0; mt < 4; mt++)
#pragma unroll
            for (int nt = 0; nt < 4; nt++)
                MMA16816(c[mt][nt], ah[mt], bh[nt>>1][(nt&1)*2], bh[nt>>1][(nt&1)*2+1]);
#pragma unroll
        for (int mt = 0; mt < 4; mt++)
#pragma unroll
            for (int nt = 0; nt < 4; nt++)
                MMA16816(c[mt][nt], al[mt], bh[nt>>1][(nt&1)*2], bh[nt>>1][(nt&1)*2+1]);
        {
            u32 bl[2][4];
#pragma unroll
            for (int np = 0; np < 2; np++)
                LDM4(bl[np], base + S2B_L + b_off + np*(16*PITCHB) + ks*32);
#pragma unroll
            for (int mt = 0; mt < 4; mt++)
#pragma unroll
                for (int nt = 0; nt < 4; nt++)
                    MMA16816(c[mt][nt], ah[mt], bl[nt>>1][(nt&1)*2], bl[nt>>1][(nt&1)*2+1]);
        }
    }
}

/* 2-pass variant for final (A hi only): AhBh + AhBl                   */
__device__ __forceinline__ void mma_chunk2f(u32 base, int wm, int wn, int lane,
                                            float c[4][4][4]){
    u32 a_off = (u32)((wm + (lane & 15))*PITCHB + (lane >> 4)*16);
    u32 b_off = (u32)((wn + (lane & 7) + ((lane >> 4) & 1)*8)*PITCHB
                      + ((lane >> 3) & 1)*16);
#pragma unroll
    for (int ks = 0; ks < 4; ks++){
        u32 ah[4][4], bh[2][4], bl[2][4];
#pragma unroll
        for (int mt = 0; mt < 4; mt++)
            LDM4(ah[mt], base + S2A_H + a_off + mt*(16*PITCHB) + ks*32);
#pragma unroll
        for (int np = 0; np < 2; np++)
            LDM4(bh[np], base + S2B_H + b_off + np*(16*PITCHB) + ks*32);
#pragma unroll
        for (int np = 0; np < 2; np++)
            LDM4(bl[np], base + S2B_L + b_off + np*(16*PITCHB) + ks*32);
#pragma unroll
        for (int mt = 0; mt < 4; mt++)
#pragma unroll
            for (int nt = 0; nt < 4; nt++)
                MMA16816(c[mt][nt], ah[mt], bh[nt>>1][(nt&1)*2], bh[nt>>1][(nt&1)*2+1]);
#pragma unroll
        for (int mt = 0; mt < 4; mt++)
#pragma unroll
            for (int nt = 0; nt < 4; nt++)
                MMA16816(c[mt][nt], ah[mt], bl[nt>>1][(nt&1)*2], bl[nt>>1][(nt&1)*2+1]);
    }
}

__device__ __forceinline__ void copy_chunk2(u32 base, int tid, int ch,
        const u32* pah, const u32* pal, const u32* pbh, const u32* pbl){
#pragma unroll
    for (int it = 0; it < 4; it++){
        int i = it*512 + tid;
        int row = i >> 3, pg = (i & 7)*4;
        size_t ga = (size_t)row*128 + ch*32 + pg;
        u32 off = base + (u32)(row*PITCHB + pg*4);
        CPA16(off + S2A_H, pah + ga);
        CPA16(off + S2A_L, pal + ga);
    }
#pragma unroll
    for (int it = 0; it < 2; it++){
        int i = it*512 + tid;
        int row = i >> 3, pg = (i & 7)*4;
        size_t gb = (size_t)row*128 + ch*32 + pg;
        u32 off = base + (u32)(row*PITCHB + pg*4);
        CPA16(off + S2B_H, pbh + gb);
        CPA16(off + S2B_L, pbl + gb);
    }
}

__device__ __forceinline__ void copy_chunk2f(u32 base, int tid, int ch,
        const u32* pah, const u32* pbh, const u32* pbl){
#pragma unroll
    for (int it = 0; it < 4; it++){
        int i = it*512 + tid;
        int row = i >> 3, pg = (i & 7)*4;
        size_t ga = (size_t)row*128 + ch*32 + pg;
        u32 off = base + (u32)(row*PITCHB + pg*4);
        CPA16(off + S2A_H, pah + ga);
    }
#pragma unroll
    for (int it = 0; it < 2; it++){
        int i = it*512 + tid;
        int row = i >> 3, pg = (i & 7)*4;
        size_t gb = (size_t)row*128 + ch*32 + pg;
        u32 off = base + (u32)(row*PITCHB + pg*4);
        CPA16(off + S2B_H, pbh + gb);
        CPA16(off + S2B_L, pbl + gb);
    }
}

__device__ __forceinline__ void gemm_pipe2(u32 smb, int tid, int wm, int wn, int lane,
        const u32* pah, const u32* pal, const u32* pbh, const u32* pbl,
        float c[4][4][4]){
    copy_chunk2(smb,        tid, 0, pah, pal, pbh, pbl);
    CP_COMMIT();
    copy_chunk2(smb + BUF2, tid, 1, pah, pal, pbh, pbl);
    CP_COMMIT();
#pragma unroll
    for (int ch = 0; ch < 4; ch++){
        if (ch < 3) CP_WAIT1(); else CP_WAIT0();
        __syncthreads();
        mma_chunk2(smb + (ch & 1)*BUF2, wm, wn, lane, c);
        __syncthreads();
        if (ch < 2){
            copy_chunk2(smb + (ch & 1)*BUF2, tid, ch + 2, pah, pal, pbh, pbl);
            CP_COMMIT();
        }
    }
}

__device__ __forceinline__ void gemm_pipe2f(u32 smb, int tid, int wm, int wn, int lane,
        const u32* pah, const u32* pbh, const u32* pbl,
        float c[4][4][4]){
    copy_chunk2f(smb,        tid, 0, pah, pbh, pbl);
    CP_COMMIT();
    copy_chunk2f(smb + BUF2, tid, 1, pah, pbh, pbl);
    CP_COMMIT();
#pragma unroll
    for (int ch = 0; ch < 4; ch++){
        if (ch < 3) CP_WAIT1(); else CP_WAIT0();
        __syncthreads();
        mma_chunk2f(smb + (ch & 1)*BUF2, wm, wn, lane, c);
        __syncthreads();
        if (ch < 2){
            copy_chunk2f(smb + (ch & 1)*BUF2, tid, ch + 2, pah, pbh, pbl);
            CP_COMMIT();
        }
    }
}

/* ------------------------------------------------------------------ */
/* K1: QKV GEMM — 256x128 tile, 512 thr, double-buffered, 3-pass.      */
/* ------------------------------------------------------------------ */
__global__ void __launch_bounds__(512, 1) k_qkv_t(){
    extern __shared__ char sm[];
    u32 smb = smem_u32(sm);
    int tid = threadIdx.x, wid = tid >> 5, lane = tid & 31;
    int oc = blockIdx.x;
    int t0 = blockIdx.y * 256;
    int wsel = oc >> 1;
    u32* dsth = (oc < 2) ? g_qh : (oc < 4 ? g_kh : g_vh);
    u32* dstl = (oc < 2) ? g_ql : (oc < 4 ? g_kl : g_vl);
    int or0 = (oc & 1) * 128;

    const u32* pah = g_xh + (size_t)t0*128;
    const u32* pal = g_xl + (size_t)t0*128;
    const u32* pbh = g_wh + (size_t)wsel*32768 + (size_t)or0*128;
    const u32* pbl = g_wl + (size_t)wsel*32768 + (size_t)or0*128;

    int wm = (wid >> 2) * 64, wn = (wid & 3) * 32;

    float c[4][4][4];
#pragma unroll
    for (int mt = 0; mt < 4; mt++)
#pragma unroll
        for (int nt = 0; nt < 4; nt++)
#pragma unroll
            for (int r = 0; r < 4; r++) c[mt][nt][r] = 0.f;

    gemm_pipe2(smb, tid, wm, wn, lane, pah, pal, pbh, pbl, c);

    u32* SH = (u32*)sm;
    u32* SL = (u32*)(sm + 69632);
#pragma unroll
    for (int mt = 0; mt < 4; mt++){
#pragma unroll
        for (int nt = 0; nt < 4; nt++){
            int r = wm + mt*16 + (lane >> 2);
            int cp = (wn + nt*8 + (lane & 3)*2) >> 1;
            u32 h, l;
            f16split2(c[mt][nt][0], c[mt][nt][1], h, l);
            SH[r*68 + cp] = h; SL[r*68 + cp] = l;
            f16split2(c[mt][nt][2], c[mt][nt][3], h, l);
            SH[(r+8)*68 + cp] = h; SL[(r+8)*68 + cp] = l;
        }
    }
    __syncthreads();
#pragma unroll
    for (int it = 0; it < 8; it++){
        int i = it*512 + tid;
        int row = i >> 4, c4 = (i & 15)*4;
        size_t g = (size_t)(t0 + row)*128 + (or0 >> 1) + c4;
        *(uint4*)&dsth[g] = *(uint4*)&SH[row*68 + c4];
        *(uint4*)&dstl[g] = *(uint4*)&SL[row*68 + c4];
    }
}

/* ------------------------------------------------------------------ */
/* K5: final GEMM — 256x128 tile, 512 thr, 2-pass (A hi only).         */
/* ------------------------------------------------------------------ */
__global__ void __launch_bounds__(512, 1) k_final_t(float* __restrict__ out){
    extern __shared__ char sm[];
    u32 smb = smem_u32(sm);
    int tid = threadIdx.x, wid = tid >> 5, lane = tid & 31;
    int o0 = blockIdx.x * 128;
    int t0 = blockIdx.y * 256;
    int b = t0 / NN, tl0 = t0 % NN;

    const u32* pah = g_ah + (size_t)t0*128;
    const u32* pbh = g_wch + (size_t)o0*128;
    const u32* pbl = g_wcl + (size_t)o0*128;

    int wm = (wid >> 2) * 64, wn = (wid & 3) * 32;

    float c[4][4][4];
#pragma unroll
    for (int mt = 0; mt < 4; mt++)
#pragma unroll
        for (int nt = 0; nt < 4; nt++)
#pragma unroll
            for (int r = 0; r < 4; r++) c[mt][nt][r] = 0.f;

    gemm_pipe2f(smb, tid, wm, wn, lane, pah, pbh, pbl, c);

    float* stage = (float*)sm;
#pragma unroll
    for (int mt = 0; mt < 4; mt++){
#pragma unroll
        for (int nt = 0; nt < 4; nt++){
            int r = wm + mt*16 + (lane >> 2);
            int cc = wn + nt*8 + (lane & 3)*2;
            stage[cc*260 + r]         = c[mt][nt][0];
            stage[(cc+1)*260 + r]     = c[mt][nt][1];
            stage[cc*260 + r + 8]     = c[mt][nt][2];
            stage[(cc+1)*260 + r + 8] = c[mt][nt][3];
        }
    }
    __syncthreads();
#pragma unroll
    for (int i2 = 0; i2 < 16; i2++){
        int idx = i2*512 + tid;
        int cc = idx >> 6, t4 = (idx & 63) * 4;
        int o = o0 + cc;
        float bias = g_bc[o];
        float4 v = *(float4*)&stage[cc*260 + t4];
        v.x += bias; v.y += bias; v.z += bias; v.w += bias;
        *(float4*)&out[((size_t)b*256 + o)*NN + tl0 + t4] = v;
    }
}

/* ------------------------------------------------------------------ */
/* K2: key-dash max — 2-pass, 2 tiles per block. grid (36, 32).        */
/* ------------------------------------------------------------------ */
__global__ void __launch_bounds__(256) k_kmax(){
    __shared__ u32 projh[128*20];
    __shared__ u32 projl[128*20];
    __shared__ u32 kth[128*20];
    __shared__ float red[256];
    int bh = blockIdx.y, b = bh >> 3, h = bh & 7;
    int t = threadIdx.x, wid = t >> 5, lane = t & 31;

#pragma unroll
    for (int r = 0; r < 2; r++){
        int i = r*256 + t;
        int m = i >> 2, q4 = (i & 3)*4;
        *(uint4*)&projh[m*20 + q4] = *(const uint4*)&g_projh[m*16 + q4];
        *(uint4*)&projl[m*20 + q4] = *(const uint4*)&g_projl[m*16 + q4];
    }

    int wm = (wid >> 1)*32, wn = (wid & 1)*64;
    u32 smPH = smem_u32(projh), smPL = smem_u32(projl);
    u32 smKH = smem_u32(kth);
    u32 a_off = (u32)((wm + (lane & 15))*80 + (lane >> 4)*16);
    u32 b_off = (u32)((wn + (lane & 7) + ((lane >> 4) & 1)*8)*80 + ((lane >> 3) & 1)*16);

    float mx = -1e30f;
    for (int tile = 0; tile < 2; tile++){
        int n0 = blockIdx.x * 256 + tile * 128;
#pragma unroll
        for (int r = 0; r < 2; r++){
            int i = r*256 + t;
            int m = i >> 2, q4 = (i & 3)*4;
            size_t g = (size_t)(b*NN + n0 + m)*128 + h*16 + q4;
            *(uint4*)&kth[m*20 + q4] = *(const uint4*)&g_kh[g];
        }
        __syncthreads();

        float c[2][8][4];
#pragma unroll
        for (int mt = 0; mt < 2; mt++)
#pragma unroll
            for (int nt = 0; nt < 8; nt++)
#pragma unroll
                for (int r = 0; r < 4; r++) c[mt][nt][r] = 0.f;
#pragma unroll
        for (int ks = 0; ks < 2; ks++){
            u32 ah[2][4], al[2][4], bh2[4][4];
#pragma unroll
            for (int mt = 0; mt < 2; mt++)
                LDM4(ah[mt], smPH + a_off + mt*(16*80) + ks*32);
#pragma unroll
            for (int np = 0; np < 4; np++)
                LDM4(bh2[np], smKH + b_off + np*(16*80) + ks*32);
#pragma unroll
            for (int mt = 0; mt < 2; mt++)
                LDM4(al[mt], smPL + a_off + mt*(16*80) + ks*32);
#pragma unroll
            for (int mt = 0; mt < 2; mt++)
#pragma unroll
                for (int nt = 0; nt < 8; nt++)
                    MMA16816(c[mt][nt], ah[mt], bh2[nt>>1][(nt&1)*2], bh2[nt>>1][(nt&1)*2+1]);
#pragma unroll
            for (int mt = 0; mt < 2; mt++)
#pragma unroll
                for (int nt = 0; nt < 8; nt++)
                    MMA16816(c[mt][nt], al[mt], bh2[nt>>1][(nt&1)*2], bh2[nt>>1][(nt&1)*2+1]);
        }
#pragma unroll
        for (int mt = 0; mt < 2; mt++)
#pragma unroll
            for (int nt = 0; nt < 8; nt++)
#pragma unroll
                for (int r = 0; r < 4; r++) mx = fmaxf(mx, c[mt][nt][r]);
        __syncthreads();
    }
    red[t] = mx;
    __syncthreads();
    for (int s = 128; s > 0; s >>= 1){
        if (t < (unsigned)s) red[t] = fmaxf(red[t], red[t + s]);
        __syncthreads();
    }
    if (t == 0) atomicMaxF(&g_kmax[bh], red[0]);
}

/* ------------------------------------------------------------------ */
/* K3: fused key features + ctx. grid (9, 32) — one full wave.         */
/* mma1 2-pass; mma2 2-pass (kps-lo dropped, no KPL at all).           */
/* ------------------------------------------------------------------ */
#define CP_PROJH 0
#define CP_PROJL 10240
#define CP_KTH   20480
#define CP_KTL   25600
#define CP_KPSH  30720
#define CP_VTH   67584
#define CP_VTL   74752
#define CP_DIAG  81920
#define CTX_SMEM 82176
#define CTX_SPLITS 9
#define CTX_TILES  16

__global__ void __launch_bounds__(256) k_ctx2(){
    extern __shared__ char sm[];
    u32 smb = smem_u32(sm);
    int bh = blockIdx.y, b = bh >> 3, h = bh & 7;
    int sp = blockIdx.x;
    int t = threadIdx.x, wid = t >> 5, lane = t & 31;
    float gmax = g_kmax[bh];

    u32* PJH = (u32*)(sm + CP_PROJH); u32* PJL = (u32*)(sm + CP_PROJL);
    u32* KTH = (u32*)(sm + CP_KTH);   u32* KTL = (u32*)(sm + CP_KTL);
    u32* VTH = (u32*)(sm + CP_VTH);   u32* VTL = (u32*)(sm + CP_VTL);
    float* DIAG = (float*)(sm + CP_DIAG);

#pragma unroll
    for (int r = 0; r < 2; r++){
        int i = r*256 + t;
        int m = i >> 2, q4 = (i & 3)*4;
        *(uint4*)&PJH[m*20 + q4] = *(const uint4*)&g_projh[m*16 + q4];
        *(uint4*)&PJL[m*20 + q4] = *(const uint4*)&g_projl[m*16 + q4];
    }
    for (int i = t; i < 1536; i += 256){
        int mat = (i >= 768), rem = (i >= 768) ? i - 768 : i;
        int tok = rem / 12, cc = 16 + rem % 12;
        u32 v = (mat == 0 && cc == 16) ? 0x00003C00u : 0u;
        ((mat == 0) ? VTH : VTL)[tok*28 + cc] = v;
    }

    int wm1 = (wid >> 1)*32, wn1 = (wid & 1)*32;
    u32 a1_off = (u32)((wm1 + (lane & 15))*80 + (lane >> 4)*16);
    u32 b1_off = (u32)((wn1 + (lane & 7) + ((lane >> 4) & 1)*8)*80 + ((lane >> 3) & 1)*16);
    int wm2 = (wid >> 1)*32, wn2 = (wid & 1)*24;
    u32 a2_off = (u32)((wm2 + (lane & 15))*144 + (lane >> 4)*16);
    u32 b2row = (u32)(((lane & 7) + ((lane >> 3) & 1)*8)*112);
    u32 b2col0 = (u32)((wn2 + ((lane >> 4) & 1)*8)*2);

    float c2[2][3][4];
#pragma unroll
    for (int mt = 0; mt < 2; mt++)
#pragma unroll
        for (int nt = 0; nt < 3; nt++)
#pragma unroll
            for (int r = 0; r < 4; r++) c2[mt][nt][r] = 0.f;

    for (int it = 0; it < CTX_TILES; it++){
        int n0 = sp*(CTX_TILES*64) + it*64;
        {
            int tok = t >> 2, q4 = (t & 3)*4;
            size_t g = (size_t)(b*NN + n0 + tok)*128 + h*16 + q4;
            *(uint4*)&KTH[tok*20 + q4] = *(const uint4*)&g_kh[g];
            *(uint4*)&KTL[tok*20 + q4] = *(const uint4*)&g_kl[g];
            *(uint4*)&VTH[tok*28 + q4] = *(const uint4*)&g_vh[g];
            *(uint4*)&VTL[tok*28 + q4] = *(const uint4*)&g_vl[g];
        }
        __syncthreads();
        if (t < 64){
            float sq = 0.f;
#pragma unroll
            for (int i = 0; i < 16; i++){
                float2 v = h2f(KTH[t*20 + i], KTL[t*20 + i]);
                sq += v.x*v.x + v.y*v.y;
            }
            DIAG[t] = HALF_NRM2 * sq;
        }
        __syncthreads();

        /* mma1: dash = projn . k  (2-pass: ph·kh + pl·kh) */
        float c1[2][4][4];
#pragma unroll
        for (int mt = 0; mt < 2; mt++)
#pragma unroll
            for (int nt = 0; nt < 4; nt++)
#pragma unroll
                for (int r = 0; r < 4; r++) c1[mt][nt][r] = 0.f;
#pragma unroll
        for (int ks = 0; ks < 2; ks++){
            u32 ah[2][4], al[2][4], bhh[2][4];
#pragma unroll
            for (int mt = 0; mt < 2; mt++)
                LDM4(ah[mt], smb + CP_PROJH + a1_off + mt*(16*80) + ks*32);
#pragma unroll
            for (int np = 0; np < 2; np++)
                LDM4(bhh[np], smb + CP_KTH + b1_off + np*(16*80) + ks*32);
#pragma unroll
            for (int mt = 0; mt < 2; mt++)
                LDM4(al[mt], smb + CP_PROJL + a1_off + mt*(16*80) + ks*32);
#pragma unroll
            for (int mt = 0; mt < 2; mt++)
#pragma unroll
                for (int nt = 0; nt < 4; nt++)
                    MMA16816(c1[mt][nt], ah[mt], bhh[nt>>1][(nt&1)*2], bhh[nt>>1][(nt&1)*2+1]);
#pragma unroll
            for (int mt = 0; mt < 2; mt++)
#pragma unroll
                for (int nt = 0; nt < 4; nt++)
                    MMA16816(c1[mt][nt], al[mt], bhh[nt>>1][(nt&1)*2], bhh[nt>>1][(nt&1)*2+1]);
        }
        u32* KPH = (u32*)(sm + CP_KPSH);
#pragma unroll
        for (int mt = 0; mt < 2; mt++){
#pragma unroll
            for (int nt = 0; nt < 4; nt++){
                int col = wn1 + nt*8 + (lane & 3)*2;
                float d0 = DIAG[col] + gmax, d1 = DIAG[col+1] + gmax;
                int r0 = wm1 + mt*16 + (lane >> 2);
                float v0 = KP_RATIO*(__expf(c1[mt][nt][0] - d0) + EPSF);
                float v1 = KP_RATIO*(__expf(c1[mt][nt][1] - d1) + EPSF);
                float v2 = KP_RATIO*(__expf(c1[mt][nt][2] - d0) + EPSF);
                float v3 = KP_RATIO*(__expf(c1[mt][nt][3] - d1) + EPSF);
                KPH[r0*36 + (col>>1)]     = f16pack2(v0, v1);
                KPH[(r0+8)*36 + (col>>1)] = f16pack2(v2, v3);
            }
        }
        __syncthreads();

        /* mma2: ctx += kps_hi . v^T (2-pass: kh·vh + kh·vl) */
#pragma unroll
        for (int ks = 0; ks < 4; ks++){
            u32 ah[2][4], bhh[2][4];
            u32 rb = (u32)(ks*16*112) + b2row;
#pragma unroll
            for (int mt = 0; mt < 2; mt++)
                LDM4(ah[mt], smb + CP_KPSH + a2_off + mt*(16*144) + ks*32);
#pragma unroll
            for (int np = 0; np < 2; np++)
                LDM4T(bhh[np], smb + CP_VTH + rb + b2col0 + np*32);
#pragma unroll
            for (int mt = 0; mt < 2; mt++)
#pragma unroll
                for (int nt = 0; nt < 3; nt++)
                    MMA16816(c2[mt][nt], ah[mt], bhh[nt>>1][(nt&1)*2], bhh[nt>>1][(nt&1)*2+1]);
            {
                u32 bl[2][4];
#pragma unroll
                for (int np = 0; np < 2; np++)
                    LDM4T(bl[np], smb + CP_VTL + rb + b2col0 + np*32);
#pragma unroll
                for (int mt = 0; mt < 2; mt++)
#pragma unroll
                    for (int nt = 0; nt < 3; nt++)
                        MMA16816(c2[mt][nt], ah[mt], bl[nt>>1][(nt&1)*2], bl[nt>>1][(nt&1)*2+1]);
            }
        }
        __syncthreads();
    }

#pragma unroll
    for (int mt = 0; mt < 2; mt++){
#pragma unroll
        for (int nt = 0; nt < 3; nt++){
            int m = wm2 + mt*16 + (lane >> 2);
            int n = wn2 + nt*8 + (lane & 3)*2;
            size_t base = ((size_t)bh*MF + m)*33;
            if (n < 33)   atomicAdd(&g_ctx[base + n],     c2[mt][nt][0]);
            if (n+1 < 33) atomicAdd(&g_ctx[base + n + 1], c2[mt][nt][1]);
            if (n < 33)   atomicAdd(&g_ctx[base + 264 + n],     c2[mt][nt][2]);
            if (n+1 < 33) atomicAdd(&g_ctx[base + 264 + n + 1], c2[mt][nt][3]);
        }
    }
}

/* ------------------------------------------------------------------ */
/* K4: fused query features + qp@ctx + d_inv. 2 tiles/block.           */
/* mma1 2-pass; mma2 2-pass (qps-lo dropped, no QPL at all).           */
/* grid (72, 32), 256 thr.                                             */
/* ------------------------------------------------------------------ */
#define QP_PROJH 0
#define QP_PROJL 10240
#define QP_QTH   20480
#define QP_QTL   25600
#define QP_QPSH  30720
#define QP_CTH   67584
#define QP_CTL   84992
#define QP_PM    102400
#define QP_RMAX  103424
#define QP_DIAG  103680
#define QP_STG   QP_QPSH
#define QA_SMEM  103936

__global__ void __launch_bounds__(256) k_qattn2(){
    extern __shared__ char sm[];
    u32 smb = smem_u32(sm);
    int bh = blockIdx.y, b = bh >> 3, h = bh & 7;
    int t = threadIdx.x, wid = t >> 5, lane = t & 31;

    u32* PJH = (u32*)(sm + QP_PROJH); u32* PJL = (u32*)(sm + QP_PROJL);
    u32* QTH = (u32*)(sm + QP_QTH);   u32* QTL = (u32*)(sm + QP_QTL);
    u32* CTH = (u32*)(sm + QP_CTH);   u32* CTL = (u32*)(sm + QP_CTL);
    float* PM = (float*)(sm + QP_PM);
    float* RMAX = (float*)(sm + QP_RMAX);
    float* DIAG = (float*)(sm + QP_DIAG);

#pragma unroll
    for (int r = 0; r < 2; r++){
        int i = r*256 + t;
        int m = i >> 2, q4 = (i & 3)*4;
        *(uint4*)&PJH[m*20 + q4] = *(const uint4*)&g_projh[m*16 + q4];
        *(uint4*)&PJL[m*20 + q4] = *(const uint4*)&g_projl[m*16 + q4];
    }
#pragma unroll
    for (int r = 0; r < 4; r++){
        int i = r*256 + t;
        int j = i >> 4, q4 = (i & 15)*4;
        *(uint4*)&CTH[j*68 + q4] = *(const uint4*)&g_ctxh2[bh*4096 + j*64 + q4];
        *(uint4*)&CTL[j*68 + q4] = *(const uint4*)&g_ctxl2[bh*4096 + j*64 + q4];
    }

    int wm1 = (wid >> 1)*32, wn1 = (wid & 1)*32;
    u32 a1_off = (u32)((wm1 + (lane & 15))*80 + (lane >> 4)*16);
    u32 b1_off = (u32)((wn1 + (lane & 7) + ((lane >> 4) & 1)*8)*80 + ((lane >> 3) & 1)*16);
    int wm2 = (wid >> 1)*16, wn2 = (wid & 1)*32;
    u32 a2_off = (u32)((wm2 + (lane & 15))*272 + (lane >> 4)*16);

    for (int tile = 0; tile < 2; tile++){
        int n0 = blockIdx.x * 128 + tile * 64;
        {
            int tok = t >> 2, q4 = (t & 3)*4;
            size_t g = (size_t)(b*NN + n0 + tok)*128 + h*16 + q4;
            *(uint4*)&QTH[tok*20 + q4] = *(const uint4*)&g_qh[g];
            *(uint4*)&QTL[tok*20 + q4] = *(const uint4*)&g_ql[g];
        }
        __syncthreads();
        if (t < 64){
            float sq = 0.f;
#pragma unroll
            for (int i = 0; i < 16; i++){
                float2 v = h2f(QTH[t*20 + i], QTL[t*20 + i]);
                sq += v.x*v.x + v.y*v.y;
            }
            DIAG[t] = HALF_NRM2 * sq;
        }
        __syncthreads();

        /* mma1: dash = projn . q (2-pass) */
        float c1[2][4][4];
#pragma unroll
        for (int mt = 0; mt < 2; mt++)
#pragma unroll
            for (int nt = 0; nt < 4; nt++)
#pragma unroll
                for (int r = 0; r < 4; r++) c1[mt][nt][r] = 0.f;
#pragma unroll
        for (int ks = 0; ks < 2; ks++){
            u32 ah[2][4], al[2][4], bhh[2][4];
#pragma unroll
            for (int mt = 0; mt < 2; mt++)
                LDM4(ah[mt], smb + QP_PROJH + a1_off + mt*(16*80) + ks*32);
#pragma unroll
            for (int np = 0; np < 2; np++)
                LDM4(bhh[np], smb + QP_QTH + b1_off + np*(16*80) + ks*32);
#pragma unroll
            for (int mt = 0; mt < 2; mt++)
                LDM4(al[mt], smb + QP_PROJL + a1_off + mt*(16*80) + ks*32);
#pragma unroll
            for (int mt = 0; mt < 2; mt++)
#pragma unroll
                for (int nt = 0; nt < 4; nt++)
                    MMA16816(c1[mt][nt], ah[mt], bhh[nt>>1][(nt&1)*2], bhh[nt>>1][(nt&1)*2+1]);
#pragma unroll
            for (int mt = 0; mt < 2; mt++)
#pragma unroll
                for (int nt = 0; nt < 4; nt++)
                    MMA16816(c1[mt][nt], al[mt], bhh[nt>>1][(nt&1)*2], bhh[nt>>1][(nt&1)*2+1]);
        }

#pragma unroll
        for (int nt = 0; nt < 4; nt++){
            float me = fmaxf(fmaxf(c1[0][nt][0], c1[0][nt][2]),
                             fmaxf(c1[1][nt][0], c1[1][nt][2]));
            float mo = fmaxf(fmaxf(c1[0][nt][1], c1[0][nt][3]),
                             fmaxf(c1[1][nt][1], c1[1][nt][3]));
#pragma unroll
            for (int s = 4; s < 32; s <<= 1){
                me = fmaxf(me, __shfl_xor_sync(0xFFFFFFFF, me, s));
                mo = fmaxf(mo, __shfl_xor_sync(0xFFFFFFFF, mo, s));
            }
            if ((lane >> 2) == 0){
                int col = wn1 + nt*8 + (lane & 3)*2;
                PM[(wid >> 1)*64 + col]     = me;
                PM[(wid >> 1)*64 + col + 1] = mo;
            }
        }
        __syncthreads();
        if (t < 64){
            float mx = PM[t];
            mx = fmaxf(mx, PM[64 + t]);
            mx = fmaxf(mx, PM[128 + t]);
            mx = fmaxf(mx, PM[192 + t]);
            RMAX[t] = mx;
        }
        __syncthreads();

        {
            u32* QPH = (u32*)(sm + QP_QPSH);
#pragma unroll
            for (int mt = 0; mt < 2; mt++){
#pragma unroll
                for (int nt = 0; nt < 4; nt++){
                    int col = wn1 + nt*8 + (lane & 3)*2;
                    float d0 = DIAG[col] + RMAX[col], d1 = DIAG[col+1] + RMAX[col+1];
                    int r0 = wm1 + mt*16 + (lane >> 2);
                    float v0 = QP_RATIO*(__expf(c1[mt][nt][0] - d0) + EPSF);
                    float v1 = QP_RATIO*(__expf(c1[mt][nt][1] - d1) + EPSF);
                    float v2 = QP_RATIO*(__expf(c1[mt][nt][2] - d0) + EPSF);
                    float v3 = QP_RATIO*(__expf(c1[mt][nt][3] - d1) + EPSF);
                    QPH[r0*36 + (col>>1)]     = f16pack2(v0, v1);
                    QPH[(r0+8)*36 + (col>>1)] = f16pack2(v2, v3);
                }
            }
        }
        __syncthreads();

        /* mma2: outT = ctx . qps_hi^T (2-pass: ch·qh + cl·qh) */
        float c2[4][4];
#pragma unroll
        for (int nt = 0; nt < 4; nt++)
#pragma unroll
            for (int r = 0; r < 4; r++) c2[nt][r] = 0.f;
#pragma unroll
        for (int ks = 0; ks < 8; ks++){
            u32 ah[4], al[4], bt[2][4];
            LDM4(ah, smb + QP_CTH + a2_off + ks*32);
            LDM4(al, smb + QP_CTL + a2_off + ks*32);
            u32 rowb = (u32)((ks*16 + (lane & 7) + ((lane >> 3) & 1)*8)*144);
#pragma unroll
            for (int np = 0; np < 2; np++){
                u32 colb = (u32)((wn2 + np*16 + ((lane >> 4) & 1)*8)*2);
                LDM4T(bt[np], smb + QP_QPSH + rowb + colb);
            }
#pragma unroll
            for (int nt = 0; nt < 4; nt++){
                MMA16816(c2[nt], ah, bt[nt>>1][(nt&1)*2], bt[nt>>1][(nt&1)*2+1]);
                MMA16816(c2[nt], al, bt[nt>>1][(nt&1)*2], bt[nt>>1][(nt&1)*2+1]);
            }
        }
        __syncthreads();

        float* STG = (float*)(sm + QP_STG);
#pragma unroll
        for (int nt = 0; nt < 4; nt++){
            int j = wm2 + (lane >> 2);
            int tok = wn2 + nt*8 + (lane & 3)*2;
            if (j <= 32){
                STG[j*68 + tok]     = c2[nt][0];
                STG[j*68 + tok + 1] = c2[nt][1];
            }
            if (j + 8 <= 32){
                STG[(j+8)*68 + tok]     = c2[nt][2];
                STG[(j+8)*68 + tok + 1] = c2[nt][3];
            }
        }
        __syncthreads();

        {
            int tok = t >> 2, jb = (t & 3)*8;
            float inv = 1.0f / STG[32*68 + tok];
            u32 hv[4], lv[4];
#pragma unroll
            for (int p = 0; p < 4; p++){
                float v0 = STG[(jb + 2*p)*68 + tok] * inv;
                float v1 = STG[(jb + 2*p + 1)*68 + tok] * inv;
                f16split2(v0, v1, hv[p], lv[p]);
            }
            size_t base = (size_t)(b*NN + n0 + tok)*128 + h*16 + (jb >> 1);
            *(uint4*)&g_ah[base] = make_uint4(hv[0], hv[1], hv[2], hv[3]);
            *(uint4*)&g_al[base] = make_uint4(lv[0], lv[1], lv[2], lv[3]);
        }
        __syncthreads();
    }
}

/* ------------------------------------------------------------------ */
extern "C" void kernel_launch(void* const* d_in, const int* in_sizes, int n_in,
                              void* d_out, int out_size){
    const float* x    = (const float*)d_in[0];
    const float* wq   = (const float*)d_in[1];
    const float* wk   = (const float*)d_in[2];
    const float* wv   = (const float*)d_in[3];
    const float* wo   = (const float*)d_in[4];
    const float* bo   = (const float*)d_in[5];
    const float* proj = (const float*)d_in[6];
    const float* wp   = (const float*)d_in[7];
    const float* bp   = (const float*)d_in[8];
    float* out = (float*)d_out;

    cudaFuncSetAttribute(k_qkv_t,   cudaFuncAttributeMaxDynamicSharedMemorySize, G4_SMEM);
    cudaFuncSetAttribute(k_final_t, cudaFuncAttributeMaxDynamicSharedMemorySize, G4_SMEM);
    cudaFuncSetAttribute(k_ctx2,    cudaFuncAttributeMaxDynamicSharedMemorySize, CTX_SMEM);
    cudaFuncSetAttribute(k_qattn2,  cudaFuncAttributeMaxDynamicSharedMemorySize, QA_SMEM);

    k_misc<<<1176, 256>>>(wq, wk, wv, proj, wo, bo, wp, bp);
    k_xcvt<<<TT/128, 256>>>(x);
    k_qkv_t<<<dim3(6, TT/256), 512, G4_SMEM>>>();
    k_kmax<<<dim3(NN/256, 32), 256>>>();
    k_ctx2<<<dim3(CTX_SPLITS, 32), 256, CTX_SMEM>>>();
    k_ctx_cvt<<<32, 256>>>();
    k_qattn2<<<dim3(NN/128, 32), 256, QA_SMEM>>>();
    k_final_t<<<dim3(2, TT/256), 512, G4_SMEM>>>(out);
}